// round 3
// baseline (speedup 1.0000x reference)
#include <cuda_runtime.h>
#include <math.h>

// ---------------- problem constants ----------------
#define B4    4
#define C0IN  64
#define C0OUT 192
#define C1OUT 576
#define NPIX  (96*96)          // 9216
#define HP    48               // pooled size

typedef unsigned long long ull;

// ---------------- scratch (device globals; no allocation allowed) ----------
__device__ float g_y [B4*C0OUT*NPIX];   // after conv0+bn+relu
__device__ float g_t [B4*C0OUT*NPIX];   // branch concat
__device__ float g_t2[B4*C1OUT*NPIX];   // after conv1+bn+relu
__device__ float g_att[B4*192*192];     // attention logits / probs
__device__ float g_o [B4*C0OUT*NPIX];   // attn @ v
__device__ float g_qn[B4*192];          // 1/||q||
__device__ float g_kn[B4*192];          // 1/||k||

// ---------------- f32x2 helpers (packed dual-FMA, SASS FFMA2) ------------
__device__ __forceinline__ ull fma2(ull a, ull b, ull c) {
    ull d;
    asm("fma.rn.f32x2 %0, %1, %2, %3;" : "=l"(d) : "l"(a), "l"(b), "l"(c));
    return d;
}
__device__ __forceinline__ ull pack2(float lo, float hi) {
    ull d;
    asm("mov.b64 %0, {%1, %2};" : "=l"(d) : "f"(lo), "f"(hi));
    return d;
}
__device__ __forceinline__ void unpack2(ull v, float& lo, float& hi) {
    asm("mov.b64 {%0, %1}, %2;" : "=f"(lo), "=f"(hi) : "l"(v));
}

// =====================================================================
// Fused 3x3 conv (pad 1) + bias + BN + ReLU, packed f32x2 math.
// Block (24, 8) = 192 threads; tile = full 96-wide x 16-tall.
// Thread computes 2 rows x 4 cols for 8 output channels.
// =====================================================================
__global__ __launch_bounds__(192) void conv3x3_bn_relu_f2(
    const float* __restrict__ in, const float* __restrict__ w,
    const float* __restrict__ bias, const float* __restrict__ gam,
    const float* __restrict__ bet, const float* __restrict__ mu,
    const float* __restrict__ var, float* __restrict__ out,
    int CI, int CO)
{
    __shared__ float  sIn[18][100];     // stride 100 keeps 16B alignment
    __shared__ float2 sW2[8][9];        // weight duplicated into both lanes
    const int tx = threadIdx.x, ty = threadIdx.y;
    const int tid = ty*24 + tx;
    const int cblk = blockIdx.z % (CO >> 3);
    const int b    = blockIdx.z / (CO >> 3);
    const int co0  = cblk * 8;
    const int y0   = blockIdx.y * 16;

    ull acc[8][2][2];
#pragma unroll
    for (int i = 0; i < 8; i++)
#pragma unroll
        for (int r = 0; r < 2; r++) { acc[i][r][0] = 0ull; acc[i][r][1] = 0ull; }

    for (int ci = 0; ci < CI; ci++) {
        __syncthreads();
        const float* ip = in + (size_t)(b*CI + ci) * NPIX;
        for (int l = tid; l < 18*98; l += 192) {
            int i = l / 98, j = l % 98;
            int gy = y0 - 1 + i, gx = j - 1;
            float v = 0.f;
            if ((unsigned)gy < 96u && (unsigned)gx < 96u) v = ip[gy*96 + gx];
            sIn[i][j] = v;
        }
        if (tid < 72) {
            float wv = w[((size_t)(co0 + tid/9)*CI + ci)*9 + tid%9];
            sW2[tid/9][tid%9] = make_float2(wv, wv);
        }
        __syncthreads();

        // Build shifted pixel pairs for 4 input rows x 6 input cols.
        ull P[4][5];
#pragma unroll
        for (int r = 0; r < 4; r++) {
            const float* row = &sIn[2*ty + r][4*tx];
            float4 v4 = *(const float4*)row;
            float2 v2 = *(const float2*)(row + 4);
            P[r][0] = pack2(v4.x, v4.y);
            P[r][1] = pack2(v4.y, v4.z);
            P[r][2] = pack2(v4.z, v4.w);
            P[r][3] = pack2(v4.w, v2.x);
            P[r][4] = pack2(v2.x, v2.y);
        }

#pragma unroll
        for (int co = 0; co < 8; co++) {
#pragma unroll
            for (int ky = 0; ky < 3; ky++)
#pragma unroll
                for (int kx = 0; kx < 3; kx++) {
                    ull wv = *(const ull*)&sW2[co][ky*3 + kx];
                    acc[co][0][0] = fma2(P[ky  ][kx  ], wv, acc[co][0][0]);
                    acc[co][0][1] = fma2(P[ky  ][kx+2], wv, acc[co][0][1]);
                    acc[co][1][0] = fma2(P[ky+1][kx  ], wv, acc[co][1][0]);
                    acc[co][1][1] = fma2(P[ky+1][kx+2], wv, acc[co][1][1]);
                }
        }
    }

    const int oy = y0 + 2*ty, ox = 4*tx;
#pragma unroll
    for (int co = 0; co < 8; co++) {
        int c = co0 + co;
        float s  = gam[c] * rsqrtf(var[c] + 1e-5f);
        float sh = (bias[c] - mu[c]) * s + bet[c];
        float* op = out + (size_t)(b*CO + c)*NPIX + oy*96 + ox;
#pragma unroll
        for (int r = 0; r < 2; r++) {
            float a0, a1, a2, a3;
            unpack2(acc[co][r][0], a0, a1);
            unpack2(acc[co][r][1], a2, a3);
            float4 o4 = make_float4(fmaxf(a0*s + sh, 0.f), fmaxf(a1*s + sh, 0.f),
                                    fmaxf(a2*s + sh, 0.f), fmaxf(a3*s + sh, 0.f));
            *(float4*)(op + r*96) = o4;
        }
    }
}

// =====================================================================
// Branch construction: t[:,0:64]   = bilinear(maxpool2(y[:,0:64]))
//                      t[:,64:128] = y[:,64:128]
//                      t[:,128:192]= bilinear(avgpool2(y[:,128:192]))
// =====================================================================
__global__ __launch_bounds__(256) void build_t_kernel()
{
    const int z = blockIdx.x;            // 0..767
    const int b = z / 192, c = z % 192;
    const float* yp = g_y + (size_t)(b*192 + c) * NPIX;
    float*       tp = g_t + (size_t)(b*192 + c) * NPIX;
    const int tid = threadIdx.x;

    if (c >= 64 && c < 128) {
        for (int i = tid; i < NPIX/4; i += 256)
            ((float4*)tp)[i] = ((const float4*)yp)[i];
        return;
    }
    __shared__ float pool[HP*HP];
    const bool is_max = (c < 64);
    for (int idx = tid; idx < HP*HP; idx += 256) {
        int p = idx / HP, q = idx % HP;
        float a  = yp[(2*p)  *96 + 2*q    ];
        float bb = yp[(2*p)  *96 + 2*q + 1];
        float cc = yp[(2*p+1)*96 + 2*q    ];
        float dd = yp[(2*p+1)*96 + 2*q + 1];
        pool[idx] = is_max ? fmaxf(fmaxf(a,bb), fmaxf(cc,dd))
                           : 0.25f*(a + bb + cc + dd);
    }
    __syncthreads();
    for (int idx = tid; idx < NPIX; idx += 256) {
        int h = idx / 96, w = idx % 96;
        float ch = fminf(fmaxf(0.5f*h - 0.25f, 0.f), 47.f);
        float cw = fminf(fmaxf(0.5f*w - 0.25f, 0.f), 47.f);
        int hlo = (int)ch; int hhi = min(hlo + 1, 47); float hf = ch - hlo;
        int wlo = (int)cw; int whi = min(wlo + 1, 47); float wf = cw - wlo;
        float top = pool[hlo*HP + wlo]*(1.f - wf) + pool[hlo*HP + whi]*wf;
        float bot = pool[hhi*HP + wlo]*(1.f - wf) + pool[hhi*HP + whi]*wf;
        tp[idx] = top*(1.f - hf) + bot*hf;
    }
}

// =====================================================================
// Row L2-norm reciprocals for q and k.
// =====================================================================
__global__ __launch_bounds__(256) void rownorm_kernel()
{
    const int x = blockIdx.x;
    const bool isK = (x >= 768);
    const int r = x % 768;
    const int b = r / 192, c = r % 192;
    const float* p = g_t2 + (size_t)(b*C1OUT + (isK ? 192 : 0) + c) * NPIX;
    const int tid = threadIdx.x;
    float s = 0.f;
    for (int i = tid; i < NPIX/4; i += 256) {
        float4 v = ((const float4*)p)[i];
        s += v.x*v.x + v.y*v.y + v.z*v.z + v.w*v.w;
    }
    __shared__ float sm[256];
    sm[tid] = s; __syncthreads();
    for (int st = 128; st > 0; st >>= 1) {
        if (tid < st) sm[tid] += sm[tid + st];
        __syncthreads();
    }
    if (tid == 0) {
        float inv = 1.f / fmaxf(sqrtf(sm[0]), 1e-12f);
        if (isK) g_kn[r] = inv; else g_qn[r] = inv;
    }
}

// =====================================================================
// S[b,i,j] = temp * qn[i] * kn[j] * sum_n Q[i,n] K[j,n]
// =====================================================================
__global__ __launch_bounds__(256) void qk_gemm_kernel(const float* __restrict__ temp)
{
    __shared__ float Qs[32][33];
    __shared__ float Ks[32][33];
    const int b = blockIdx.z;
    const int i0 = blockIdx.y * 32, j0 = blockIdx.x * 32;
    const float* Q = g_t2 + (size_t)b * C1OUT * NPIX;
    const float* K = Q + (size_t)192 * NPIX;
    const int tx = threadIdx.x, ty = threadIdx.y;
    const int tid = ty*16 + tx;
    float acc[2][2] = {{0.f,0.f},{0.f,0.f}};

    for (int kt = 0; kt < NPIX; kt += 32) {
        __syncthreads();
        for (int l = tid; l < 1024; l += 256) {
            int rr = l >> 5, cc = l & 31;
            Qs[cc][rr] = Q[(size_t)(i0 + rr)*NPIX + kt + cc];
            Ks[cc][rr] = K[(size_t)(j0 + rr)*NPIX + kt + cc];
        }
        __syncthreads();
#pragma unroll
        for (int kk = 0; kk < 32; kk++) {
            float q0 = Qs[kk][2*ty], q1 = Qs[kk][2*ty+1];
            float k0 = Ks[kk][2*tx], k1 = Ks[kk][2*tx+1];
            acc[0][0] += q0*k0; acc[0][1] += q0*k1;
            acc[1][0] += q1*k0; acc[1][1] += q1*k1;
        }
    }
    float tmp = temp[0];
#pragma unroll
    for (int di = 0; di < 2; di++) {
        int i = i0 + 2*ty + di;
        float qs = g_qn[b*192 + i] * tmp;
#pragma unroll
        for (int dj = 0; dj < 2; dj++) {
            int j = j0 + 2*tx + dj;
            g_att[(size_t)(b*192 + i)*192 + j] = acc[di][dj] * qs * g_kn[b*192 + j];
        }
    }
}

// =====================================================================
// Softmax over last dim (192).
// =====================================================================
__global__ __launch_bounds__(256) void softmax_kernel()
{
    const int row = blockIdx.x;          // 0..767
    float* p = g_att + (size_t)row * 192;
    const int t = threadIdx.x;
    __shared__ float sm[256];
    float v = (t < 192) ? p[t] : -3.0e38f;
    sm[t] = v; __syncthreads();
    for (int s = 128; s > 0; s >>= 1) {
        if (t < s) sm[t] = fmaxf(sm[t], sm[t+s]);
        __syncthreads();
    }
    float mx = sm[0]; __syncthreads();
    float e = (t < 192) ? expf(v - mx) : 0.f;
    sm[t] = e; __syncthreads();
    for (int s = 128; s > 0; s >>= 1) {
        if (t < s) sm[t] += sm[t+s];
        __syncthreads();
    }
    float inv = 1.f / sm[0];
    if (t < 192) p[t] = e * inv;
}

// =====================================================================
// O[b,i,n] = sum_j A[b,i,j] V[b,j,n]   (M=192, K=192, N=9216)
// =====================================================================
__global__ __launch_bounds__(256) void av_gemm_kernel()
{
    __shared__ float As[32][33];
    __shared__ float Vs[32][64];
    const int b = blockIdx.z;
    const int n0 = blockIdx.x * 64, i0 = blockIdx.y * 32;
    const float* A = g_att + (size_t)b * 192 * 192;
    const float* V = g_t2 + (size_t)b * C1OUT * NPIX + (size_t)384 * NPIX;
    const int tx = threadIdx.x, ty = threadIdx.y;
    const int tid = ty*16 + tx;
    float acc[2][4];
#pragma unroll
    for (int i = 0; i < 2; i++)
#pragma unroll
        for (int j = 0; j < 4; j++) acc[i][j] = 0.f;

    for (int kt = 0; kt < 192; kt += 32) {
        __syncthreads();
        for (int l = tid; l < 1024; l += 256) {
            int rr = l >> 5, cc = l & 31;
            As[cc][rr] = A[(size_t)(i0 + rr)*192 + kt + cc];
        }
        for (int l = tid; l < 512; l += 256) {
            int kk = l >> 4, nn = (l & 15) * 4;
            *(float4*)&Vs[kk][nn] = *(const float4*)&V[(size_t)(kt + kk)*NPIX + n0 + nn];
        }
        __syncthreads();
#pragma unroll
        for (int kk = 0; kk < 32; kk++) {
            float a0 = As[kk][2*ty], a1 = As[kk][2*ty+1];
            float4 vv = *(const float4*)&Vs[kk][tx*4];
            acc[0][0] += a0*vv.x; acc[0][1] += a0*vv.y;
            acc[0][2] += a0*vv.z; acc[0][3] += a0*vv.w;
            acc[1][0] += a1*vv.x; acc[1][1] += a1*vv.y;
            acc[1][2] += a1*vv.z; acc[1][3] += a1*vv.w;
        }
    }
#pragma unroll
    for (int di = 0; di < 2; di++) {
        float4 o4 = make_float4(acc[di][0], acc[di][1], acc[di][2], acc[di][3]);
        *(float4*)&g_o[(size_t)(b*192 + i0 + 2*ty + di)*NPIX + n0 + tx*4] = o4;
    }
}

// =====================================================================
// Depthwise 3x3 conv (pad 1) + bias on g_o -> d_out.
// =====================================================================
__global__ __launch_bounds__(256) void dwconv_kernel(
    const float* __restrict__ w2, const float* __restrict__ b2,
    float* __restrict__ out)
{
    __shared__ float sIn[34][34];
    const int tx = threadIdx.x, ty = threadIdx.y;
    const int tid = ty*16 + tx;
    const int z = blockIdx.z;            // 0..767
    const int b = z / 192, c = z % 192;
    const int y0 = blockIdx.y*32, x0 = blockIdx.x*32;
    const float* ip = g_o + (size_t)(b*192 + c) * NPIX;

    for (int l = tid; l < 34*34; l += 256) {
        int i = l / 34, j = l % 34;
        int gy = y0 - 1 + i, gx = x0 - 1 + j;
        float v = 0.f;
        if ((unsigned)gy < 96u && (unsigned)gx < 96u) v = ip[gy*96 + gx];
        ((float*)sIn)[l] = v;
    }
    __syncthreads();

    float wv[9];
#pragma unroll
    for (int k = 0; k < 9; k++) wv[k] = w2[c*9 + k];
    float bb = b2[c];

    float iv[4][4];
#pragma unroll
    for (int r = 0; r < 4; r++)
#pragma unroll
        for (int cc = 0; cc < 4; cc++) iv[r][cc] = sIn[2*ty + r][2*tx + cc];

    float a00 = bb, a01 = bb, a10 = bb, a11 = bb;
#pragma unroll
    for (int ky = 0; ky < 3; ky++)
#pragma unroll
        for (int kx = 0; kx < 3; kx++) {
            float wk = wv[ky*3 + kx];
            a00 += iv[ky  ][kx  ]*wk;
            a01 += iv[ky  ][kx+1]*wk;
            a10 += iv[ky+1][kx  ]*wk;
            a11 += iv[ky+1][kx+1]*wk;
        }
    const int oy = y0 + 2*ty, ox = x0 + 2*tx;
    float* op = out + (size_t)(b*192 + c)*NPIX + oy*96 + ox;
    op[0] = a00; op[1] = a01; op[96] = a10; op[97] = a11;
}

// =====================================================================
// Launcher
// =====================================================================
extern "C" void kernel_launch(void* const* d_in, const int* in_sizes, int n_in,
                              void* d_out, int out_size)
{
    const float* x    = (const float*)d_in[0];
    const float* w0   = (const float*)d_in[1];
    const float* b0   = (const float*)d_in[2];
    const float* g0   = (const float*)d_in[3];
    const float* be0  = (const float*)d_in[4];
    const float* m0   = (const float*)d_in[5];
    const float* v0   = (const float*)d_in[6];
    const float* w1   = (const float*)d_in[7];
    const float* b1   = (const float*)d_in[8];
    const float* g1   = (const float*)d_in[9];
    const float* be1  = (const float*)d_in[10];
    const float* m1   = (const float*)d_in[11];
    const float* v1   = (const float*)d_in[12];
    const float* temp = (const float*)d_in[13];
    const float* w2   = (const float*)d_in[14];
    const float* b2   = (const float*)d_in[15];
    float* out = (float*)d_out;

    float *py, *pt, *pt2;
    cudaGetSymbolAddress((void**)&py,  g_y);
    cudaGetSymbolAddress((void**)&pt,  g_t);
    cudaGetSymbolAddress((void**)&pt2, g_t2);

    dim3 cblk(24, 8);

    // conv0 + bn + relu : x -> g_y
    conv3x3_bn_relu_f2<<<dim3(1, 6, B4 * (C0OUT/8)), cblk>>>(
        x, w0, b0, g0, be0, m0, v0, py, C0IN, C0OUT);

    // branches -> g_t
    build_t_kernel<<<B4*192, 256>>>();

    // conv1 + bn + relu : g_t -> g_t2
    conv3x3_bn_relu_f2<<<dim3(1, 6, B4 * (C1OUT/8)), cblk>>>(
        pt, w1, b1, g1, be1, m1, v1, pt2, C0OUT, C1OUT);

    // q/k row norms
    rownorm_kernel<<<2*B4*192, 256>>>();

    // attention logits
    qk_gemm_kernel<<<dim3(6, 6, B4), dim3(16,16)>>>(temp);

    // softmax
    softmax_kernel<<<B4*192, 256>>>();

    // attn @ v
    av_gemm_kernel<<<dim3(144, 6, B4), dim3(16,16)>>>();

    // depthwise conv + bias -> output
    dwconv_kernel<<<dim3(3, 3, B4*192), dim3(16,16)>>>(w2, b2, out);
}

// round 5
// speedup vs baseline: 4.0106x; 4.0106x over previous
#include <cuda_runtime.h>
#include <math.h>
#include <stdint.h>

// ---------------- problem constants ----------------
#define B4    4
#define C0IN  64
#define C0OUT 192
#define C1OUT 576
#define NPIX  (96*96)          // 9216
#define PDIM  98
#define PPIX  (98*98)          // 9604
#define HP    48               // pooled size

// ---------------- scratch (device globals; no allocation allowed) ----------
__device__ float g_xp[B4*C0IN *PPIX];   // padded input x
__device__ float g_y [B4*C0OUT*NPIX];   // after conv0+bn+relu
__device__ float g_tp[B4*C0OUT*PPIX];   // padded branch concat (conv1 input)
__device__ float g_t2[B4*C1OUT*NPIX];   // after conv1+bn+relu
__device__ float g_att[B4*192*192];     // attention logits / probs
__device__ float g_o [B4*C0OUT*NPIX];   // attn @ v
__device__ float g_qn[B4*192];          // 1/||q||
__device__ float g_kn[B4*192];          // 1/||k||

// ---------------- tf32 helpers ----------------
__device__ __forceinline__ uint32_t f2tf(float f) {
    uint32_t r;
    asm("cvt.rna.tf32.f32 %0, %1;" : "=r"(r) : "f"(f));
    return r;
}
__device__ __forceinline__ void mma_tf32(float c[4],
    uint32_t a0, uint32_t a1, uint32_t a2, uint32_t a3,
    uint32_t b0, uint32_t b1)
{
    asm volatile(
        "mma.sync.aligned.m16n8k8.row.col.f32.tf32.tf32.f32 "
        "{%0,%1,%2,%3}, {%4,%5,%6,%7}, {%8,%9}, {%0,%1,%2,%3};"
        : "+f"(c[0]), "+f"(c[1]), "+f"(c[2]), "+f"(c[3])
        : "r"(a0), "r"(a1), "r"(a2), "r"(a3), "r"(b0), "r"(b1));
}

// =====================================================================
// Implicit-GEMM 3x3 conv (padded input) + bias + BN + ReLU, tf32 MMA.
// Tile: M=64 output channels x N=384 pixels (4 image rows).
// 8 warps = 2(M) x 4(N); warp = 2 x m16 tiles x 12 x n8 tiles.
// K loop: 8 input channels per chunk x 9 shifts.
// =====================================================================
__global__ __launch_bounds__(256) void conv3x3_mma(
    const float* __restrict__ in,   // padded [B, CI, 98, 98]
    const float* __restrict__ w,    // [CO, CI, 3, 3]
    const float* __restrict__ bias, const float* __restrict__ gam,
    const float* __restrict__ bet,  const float* __restrict__ mu,
    const float* __restrict__ var,  float* __restrict__ out, // [B, CO, 96, 96]
    int CI, int CO)
{
    __shared__ uint32_t sW[9][64][8];     // [shift][co][ci_k]   18 KB
    __shared__ uint32_t sX[8][6][104];    // [ci_k][pad_row][col] 20 KB

    const int tid  = threadIdx.x;
    const int warp = tid >> 5;
    const int lane = tid & 31;
    const int g    = lane >> 2;           // groupID 0..7
    const int tig  = lane & 3;            // 0..3
    const int wm   = warp >> 2;           // 0..1  (M)
    const int wn   = warp & 3;            // 0..3  (N: one image row each)

    const int y0o = blockIdx.x * 4;       // first output row of tile
    const int co0 = blockIdx.y * 64;
    const int b   = blockIdx.z;

    float acc[2][12][4];
#pragma unroll
    for (int mi = 0; mi < 2; mi++)
#pragma unroll
        for (int ni = 0; ni < 12; ni++)
#pragma unroll
            for (int q = 0; q < 4; q++) acc[mi][ni][q] = 0.f;

    const float* inb = in + (size_t)b * CI * PPIX;

    for (int ci0 = 0; ci0 < CI; ci0 += 8) {
        __syncthreads();
        // weights: sW[rs][co][k]
        for (int l = tid; l < 4608; l += 256) {
            int rs = l >> 9, rem = l & 511;
            int co = rem >> 3, k = rem & 7;
            ((uint32_t*)sW)[l] = 0;  // dummy to keep layout obvious (overwritten)
            sW[rs][co][k] = f2tf(w[((size_t)(co0 + co)*CI + ci0 + k)*9 + rs]);
        }
        // input: padded rows y0o .. y0o+5, cols 0..97, 8 channels
        for (int l = tid; l < 8*6*98; l += 256) {
            int k = l / 588, rem = l % 588;
            int row = rem / 98, col = rem % 98;
            sX[k][row][col] = f2tf(inb[(size_t)(ci0 + k)*PPIX + (y0o + row)*PDIM + col]);
        }
        __syncthreads();

#pragma unroll
        for (int r = 0; r < 3; r++) {
#pragma unroll
            for (int s = 0; s < 3; s++) {
                const int rs = r*3 + s;
                uint32_t A0[4], A1[4];
                {
                    int base0 = wm*32 + g;
                    A0[0] = sW[rs][base0     ][tig];
                    A0[1] = sW[rs][base0 +  8][tig];
                    A0[2] = sW[rs][base0     ][tig+4];
                    A0[3] = sW[rs][base0 +  8][tig+4];
                    A1[0] = sW[rs][base0 + 16][tig];
                    A1[1] = sW[rs][base0 + 24][tig];
                    A1[2] = sW[rs][base0 + 16][tig+4];
                    A1[3] = sW[rs][base0 + 24][tig+4];
                }
                const int prow = wn + r;
#pragma unroll
                for (int ni = 0; ni < 12; ni++) {
                    int col = ni*8 + g + s;
                    uint32_t b0 = sX[tig  ][prow][col];
                    uint32_t b1 = sX[tig+4][prow][col];
                    mma_tf32(acc[0][ni], A0[0], A0[1], A0[2], A0[3], b0, b1);
                    mma_tf32(acc[1][ni], A1[0], A1[1], A1[2], A1[3], b0, b1);
                }
            }
        }
    }

    // epilogue: BN + ReLU, write [B, CO, 96, 96]
    const int orow = y0o + wn;
#pragma unroll
    for (int mi = 0; mi < 2; mi++) {
        int c_lo = co0 + wm*32 + mi*16 + g;
        int c_hi = c_lo + 8;
        float s_lo  = gam[c_lo] * rsqrtf(var[c_lo] + 1e-5f);
        float sh_lo = (bias[c_lo] - mu[c_lo]) * s_lo + bet[c_lo];
        float s_hi  = gam[c_hi] * rsqrtf(var[c_hi] + 1e-5f);
        float sh_hi = (bias[c_hi] - mu[c_hi]) * s_hi + bet[c_hi];
        float* plo = out + (size_t)(b*CO + c_lo)*NPIX + orow*96;
        float* phi = out + (size_t)(b*CO + c_hi)*NPIX + orow*96;
#pragma unroll
        for (int ni = 0; ni < 12; ni++) {
            int x = ni*8 + tig*2;
            float2 v0 = make_float2(fmaxf(acc[mi][ni][0]*s_lo + sh_lo, 0.f),
                                    fmaxf(acc[mi][ni][1]*s_lo + sh_lo, 0.f));
            float2 v1 = make_float2(fmaxf(acc[mi][ni][2]*s_hi + sh_hi, 0.f),
                                    fmaxf(acc[mi][ni][3]*s_hi + sh_hi, 0.f));
            *(float2*)(plo + x) = v0;
            *(float2*)(phi + x) = v1;
        }
    }
}

// =====================================================================
// Pad x -> g_xp [B, 64, 98, 98] with zero border.
// =====================================================================
__global__ __launch_bounds__(256) void pad_x_kernel(const float* __restrict__ x)
{
    const int z = blockIdx.x;                 // b*64 + c
    const float* sp = x + (size_t)z * NPIX;
    float* dp = g_xp + (size_t)z * PPIX;
    for (int i = threadIdx.x; i < PPIX; i += 256) {
        int row = i / PDIM, col = i % PDIM;
        float v = 0.f;
        if (row >= 1 && row <= 96 && col >= 1 && col <= 96)
            v = sp[(row-1)*96 + (col-1)];
        dp[i] = v;
    }
}

// =====================================================================
// Branch construction into PADDED g_tp:
//  c in [0,64):    bilinear(maxpool2(y))
//  c in [64,128):  copy y
//  c in [128,192): bilinear(avgpool2(y))
// Border of each padded plane zeroed.
// =====================================================================
__global__ __launch_bounds__(256) void build_t_kernel()
{
    const int z = blockIdx.x;            // 0..767
    const int b = z / 192, c = z % 192;
    const float* yp = g_y  + (size_t)(b*192 + c) * NPIX;
    float*       tp = g_tp + (size_t)(b*192 + c) * PPIX;
    const int tid = threadIdx.x;

    if (c >= 64 && c < 128) {
        for (int i = tid; i < PPIX; i += 256) {
            int row = i / PDIM, col = i % PDIM;
            float v = 0.f;
            if (row >= 1 && row <= 96 && col >= 1 && col <= 96)
                v = yp[(row-1)*96 + (col-1)];
            tp[i] = v;
        }
        return;
    }
    __shared__ float pool[HP*HP];
    const bool is_max = (c < 64);
    for (int idx = tid; idx < HP*HP; idx += 256) {
        int p = idx / HP, q = idx % HP;
        float a  = yp[(2*p)  *96 + 2*q    ];
        float bb = yp[(2*p)  *96 + 2*q + 1];
        float cc = yp[(2*p+1)*96 + 2*q    ];
        float dd = yp[(2*p+1)*96 + 2*q + 1];
        pool[idx] = is_max ? fmaxf(fmaxf(a,bb), fmaxf(cc,dd))
                           : 0.25f*(a + bb + cc + dd);
    }
    __syncthreads();
    for (int i = tid; i < PPIX; i += 256) {
        int row = i / PDIM, col = i % PDIM;
        if (row < 1 || row > 96 || col < 1 || col > 96) { tp[i] = 0.f; continue; }
        int h = row - 1, w = col - 1;
        float ch = fminf(fmaxf(0.5f*h - 0.25f, 0.f), 47.f);
        float cw = fminf(fmaxf(0.5f*w - 0.25f, 0.f), 47.f);
        int hlo = (int)ch; int hhi = min(hlo + 1, 47); float hf = ch - hlo;
        int wlo = (int)cw; int whi = min(wlo + 1, 47); float wf = cw - wlo;
        float top = pool[hlo*HP + wlo]*(1.f - wf) + pool[hlo*HP + whi]*wf;
        float bot = pool[hhi*HP + wlo]*(1.f - wf) + pool[hhi*HP + whi]*wf;
        tp[i] = top*(1.f - hf) + bot*hf;
    }
}

// =====================================================================
// Row L2-norm reciprocals for q and k.
// =====================================================================
__global__ __launch_bounds__(256) void rownorm_kernel()
{
    const int x = blockIdx.x;
    const bool isK = (x >= 768);
    const int r = x % 768;
    const int b = r / 192, c = r % 192;
    const float* p = g_t2 + (size_t)(b*C1OUT + (isK ? 192 : 0) + c) * NPIX;
    const int tid = threadIdx.x;
    float s = 0.f;
    for (int i = tid; i < NPIX/4; i += 256) {
        float4 v = ((const float4*)p)[i];
        s += v.x*v.x + v.y*v.y + v.z*v.z + v.w*v.w;
    }
    __shared__ float sm[256];
    sm[tid] = s; __syncthreads();
    for (int st = 128; st > 0; st >>= 1) {
        if (tid < st) sm[tid] += sm[tid + st];
        __syncthreads();
    }
    if (tid == 0) {
        float inv = 1.f / fmaxf(sqrtf(sm[0]), 1e-12f);
        if (isK) g_kn[r] = inv; else g_qn[r] = inv;
    }
}

// =====================================================================
// S[b,i,j] = temp * qn[i] * kn[j] * sum_n Q[i,n] K[j,n]
// =====================================================================
__global__ __launch_bounds__(256) void qk_gemm_kernel(const float* __restrict__ temp)
{
    __shared__ float Qs[32][33];
    __shared__ float Ks[32][33];
    const int b = blockIdx.z;
    const int i0 = blockIdx.y * 32, j0 = blockIdx.x * 32;
    const float* Q = g_t2 + (size_t)b * C1OUT * NPIX;
    const float* K = Q + (size_t)192 * NPIX;
    const int tx = threadIdx.x, ty = threadIdx.y;
    const int tid = ty*16 + tx;
    float acc[2][2] = {{0.f,0.f},{0.f,0.f}};

    for (int kt = 0; kt < NPIX; kt += 32) {
        __syncthreads();
        for (int l = tid; l < 1024; l += 256) {
            int rr = l >> 5, cc = l & 31;
            Qs[cc][rr] = Q[(size_t)(i0 + rr)*NPIX + kt + cc];
            Ks[cc][rr] = K[(size_t)(j0 + rr)*NPIX + kt + cc];
        }
        __syncthreads();
#pragma unroll
        for (int kk = 0; kk < 32; kk++) {
            float q0 = Qs[kk][2*ty], q1 = Qs[kk][2*ty+1];
            float k0 = Ks[kk][2*tx], k1 = Ks[kk][2*tx+1];
            acc[0][0] += q0*k0; acc[0][1] += q0*k1;
            acc[1][0] += q1*k0; acc[1][1] += q1*k1;
        }
    }
    float tmp = temp[0];
#pragma unroll
    for (int di = 0; di < 2; di++) {
        int i = i0 + 2*ty + di;
        float qs = g_qn[b*192 + i] * tmp;
#pragma unroll
        for (int dj = 0; dj < 2; dj++) {
            int j = j0 + 2*tx + dj;
            g_att[(size_t)(b*192 + i)*192 + j] = acc[di][dj] * qs * g_kn[b*192 + j];
        }
    }
}

// =====================================================================
// Softmax over last dim (192).
// =====================================================================
__global__ __launch_bounds__(256) void softmax_kernel()
{
    const int row = blockIdx.x;          // 0..767
    float* p = g_att + (size_t)row * 192;
    const int t = threadIdx.x;
    __shared__ float sm[256];
    float v = (t < 192) ? p[t] : -3.0e38f;
    sm[t] = v; __syncthreads();
    for (int s = 128; s > 0; s >>= 1) {
        if (t < s) sm[t] = fmaxf(sm[t], sm[t+s]);
        __syncthreads();
    }
    float mx = sm[0]; __syncthreads();
    float e = (t < 192) ? expf(v - mx) : 0.f;
    sm[t] = e; __syncthreads();
    for (int s = 128; s > 0; s >>= 1) {
        if (t < s) sm[t] += sm[t+s];
        __syncthreads();
    }
    float inv = 1.f / sm[0];
    if (t < 192) p[t] = e * inv;
}

// =====================================================================
// O[b,i,n] = sum_j A[b,i,j] V[b,j,n]   (M=192, K=192, N=9216)
// =====================================================================
__global__ __launch_bounds__(256) void av_gemm_kernel()
{
    __shared__ float As[32][33];
    __shared__ float Vs[32][64];
    const int b = blockIdx.z;
    const int n0 = blockIdx.x * 64, i0 = blockIdx.y * 32;
    const float* A = g_att + (size_t)b * 192 * 192;
    const float* V = g_t2 + (size_t)b * C1OUT * NPIX + (size_t)384 * NPIX;
    const int tx = threadIdx.x, ty = threadIdx.y;
    const int tid = ty*16 + tx;
    float acc[2][4];
#pragma unroll
    for (int i = 0; i < 2; i++)
#pragma unroll
        for (int j = 0; j < 4; j++) acc[i][j] = 0.f;

    for (int kt = 0; kt < 192; kt += 32) {
        __syncthreads();
        for (int l = tid; l < 1024; l += 256) {
            int rr = l >> 5, cc = l & 31;
            As[cc][rr] = A[(size_t)(i0 + rr)*192 + kt + cc];
        }
        for (int l = tid; l < 512; l += 256) {
            int kk = l >> 4, nn = (l & 15) * 4;
            *(float4*)&Vs[kk][nn] = *(const float4*)&V[(size_t)(kt + kk)*NPIX + n0 + nn];
        }
        __syncthreads();
#pragma unroll
        for (int kk = 0; kk < 32; kk++) {
            float a0 = As[kk][2*ty], a1 = As[kk][2*ty+1];
            float4 vv = *(const float4*)&Vs[kk][tx*4];
            acc[0][0] += a0*vv.x; acc[0][1] += a0*vv.y;
            acc[0][2] += a0*vv.z; acc[0][3] += a0*vv.w;
            acc[1][0] += a1*vv.x; acc[1][1] += a1*vv.y;
            acc[1][2] += a1*vv.z; acc[1][3] += a1*vv.w;
        }
    }
#pragma unroll
    for (int di = 0; di < 2; di++) {
        float4 o4 = make_float4(acc[di][0], acc[di][1], acc[di][2], acc[di][3]);
        *(float4*)&g_o[(size_t)(b*192 + i0 + 2*ty + di)*NPIX + n0 + tx*4] = o4;
    }
}

// =====================================================================
// Depthwise 3x3 conv (pad 1) + bias on g_o -> d_out.
// =====================================================================
__global__ __launch_bounds__(256) void dwconv_kernel(
    const float* __restrict__ w2, const float* __restrict__ b2,
    float* __restrict__ out)
{
    __shared__ float sIn[34][34];
    const int tx = threadIdx.x, ty = threadIdx.y;
    const int tid = ty*16 + tx;
    const int z = blockIdx.z;            // 0..767
    const int b = z / 192, c = z % 192;
    const int y0 = blockIdx.y*32, x0 = blockIdx.x*32;
    const float* ip = g_o + (size_t)(b*192 + c) * NPIX;

    for (int l = tid; l < 34*34; l += 256) {
        int i = l / 34, j = l % 34;
        int gy = y0 - 1 + i, gx = x0 - 1 + j;
        float v = 0.f;
        if ((unsigned)gy < 96u && (unsigned)gx < 96u) v = ip[gy*96 + gx];
        ((float*)sIn)[l] = v;
    }
    __syncthreads();

    float wv[9];
#pragma unroll
    for (int k = 0; k < 9; k++) wv[k] = w2[c*9 + k];
    float bb = b2[c];

    float iv[4][4];
#pragma unroll
    for (int r = 0; r < 4; r++)
#pragma unroll
        for (int cc = 0; cc < 4; cc++) iv[r][cc] = sIn[2*ty + r][2*tx + cc];

    float a00 = bb, a01 = bb, a10 = bb, a11 = bb;
#pragma unroll
    for (int ky = 0; ky < 3; ky++)
#pragma unroll
        for (int kx = 0; kx < 3; kx++) {
            float wk = wv[ky*3 + kx];
            a00 += iv[ky  ][kx  ]*wk;
            a01 += iv[ky  ][kx+1]*wk;
            a10 += iv[ky+1][kx  ]*wk;
            a11 += iv[ky+1][kx+1]*wk;
        }
    const int oy = y0 + 2*ty, ox = x0 + 2*tx;
    float* op = out + (size_t)(b*192 + c)*NPIX + oy*96 + ox;
    op[0] = a00; op[1] = a01; op[96] = a10; op[97] = a11;
}

// =====================================================================
// Launcher
// =====================================================================
extern "C" void kernel_launch(void* const* d_in, const int* in_sizes, int n_in,
                              void* d_out, int out_size)
{
    const float* x    = (const float*)d_in[0];
    const float* w0   = (const float*)d_in[1];
    const float* b0   = (const float*)d_in[2];
    const float* g0   = (const float*)d_in[3];
    const float* be0  = (const float*)d_in[4];
    const float* m0   = (const float*)d_in[5];
    const float* v0   = (const float*)d_in[6];
    const float* w1   = (const float*)d_in[7];
    const float* b1   = (const float*)d_in[8];
    const float* g1   = (const float*)d_in[9];
    const float* be1  = (const float*)d_in[10];
    const float* m1   = (const float*)d_in[11];
    const float* v1   = (const float*)d_in[12];
    const float* temp = (const float*)d_in[13];
    const float* w2   = (const float*)d_in[14];
    const float* b2   = (const float*)d_in[15];
    float* out = (float*)d_out;

    float *pxp, *py, *ptp, *pt2;
    cudaGetSymbolAddress((void**)&pxp, g_xp);
    cudaGetSymbolAddress((void**)&py,  g_y);
    cudaGetSymbolAddress((void**)&ptp, g_tp);
    cudaGetSymbolAddress((void**)&pt2, g_t2);

    // pad x -> g_xp
    pad_x_kernel<<<B4*C0IN, 256>>>(x);

    // conv0 + bn + relu : g_xp -> g_y   (MMA implicit GEMM)
    conv3x3_mma<<<dim3(24, C0OUT/64, B4), 256>>>(
        pxp, w0, b0, g0, be0, m0, v0, py, C0IN, C0OUT);

    // branches -> padded g_tp
    build_t_kernel<<<B4*192, 256>>>();

    // conv1 + bn + relu : g_tp -> g_t2  (MMA implicit GEMM)
    conv3x3_mma<<<dim3(24, C1OUT/64, B4), 256>>>(
        ptp, w1, b1, g1, be1, m1, v1, pt2, C0OUT, C1OUT);

    // q/k row norms
    rownorm_kernel<<<2*B4*192, 256>>>();

    // attention logits
    qk_gemm_kernel<<<dim3(6, 6, B4), dim3(16,16)>>>(temp);

    // softmax
    softmax_kernel<<<B4*192, 256>>>();

    // attn @ v
    av_gemm_kernel<<<dim3(144, 6, B4), dim3(16,16)>>>();

    // depthwise conv + bias -> output
    dwconv_kernel<<<dim3(3, 3, B4*192), dim3(16,16)>>>(w2, b2, out);
}

// round 6
// speedup vs baseline: 7.2635x; 1.8111x over previous
#include <cuda_runtime.h>
#include <math.h>
#include <stdint.h>

// ---------------- problem constants ----------------
#define B4    4
#define C0IN  64
#define C0OUT 192
#define C1OUT 576
#define NPIX  (96*96)          // 9216
#define PDIM  98
#define PPIX  (98*98)          // 9604
#define HP    48               // pooled size

// ---------------- scratch (device globals; no allocation allowed) ----------
__device__ float g_xp [B4*C0IN *PPIX];   // padded input x (tf32 bits)
__device__ float g_y  [B4*C0OUT*NPIX];   // after conv0+bn+relu (fp32)
__device__ float g_tp [B4*C0OUT*PPIX];   // padded branch concat (tf32 bits)
__device__ float g_t2 [B4*C1OUT*NPIX];   // after conv1+bn+relu (fp32)
__device__ float g_att[B4*192*192];      // attention logits / probs
__device__ float g_o  [B4*C0OUT*NPIX];   // attn @ v
__device__ float g_qn [B4*192];          // 1/||q||
__device__ float g_kn [B4*192];          // 1/||k||
__device__ float g_w0t[C0OUT*C0IN*9];    // repacked tf32 weights conv0
__device__ float g_w1t[C1OUT*C0OUT*9];   // repacked tf32 weights conv1

// ---------------- tf32 helpers ----------------
__device__ __forceinline__ uint32_t f2tf(float f) {
    uint32_t r;
    asm("cvt.rna.tf32.f32 %0, %1;" : "=r"(r) : "f"(f));
    return r;
}
__device__ __forceinline__ void mma_tf32(float c[4],
    uint32_t a0, uint32_t a1, uint32_t a2, uint32_t a3,
    uint32_t b0, uint32_t b1)
{
    asm volatile(
        "mma.sync.aligned.m16n8k8.row.col.f32.tf32.tf32.f32 "
        "{%0,%1,%2,%3}, {%4,%5,%6,%7}, {%8,%9}, {%0,%1,%2,%3};"
        : "+f"(c[0]), "+f"(c[1]), "+f"(c[2]), "+f"(c[3])
        : "r"(a0), "r"(a1), "r"(a2), "r"(a3), "r"(b0), "r"(b1));
}

// =====================================================================
// Weight repack: w[CO,CI,3,3] fp32 -> tf32 bits, layout
// out[((chunk*9 + rs)*CO + co)*8 + pos], pos pairs (k,k+4) interleaved.
// =====================================================================
__global__ __launch_bounds__(256) void repack_w_kernel(
    const float* __restrict__ w, float* __restrict__ outf, int CI, int CO)
{
    uint32_t* out = (uint32_t*)outf;
    const int total = CO * CI * 9;
    for (int d = blockIdx.x*256 + threadIdx.x; d < total; d += gridDim.x*256) {
        int pos = d & 7;
        int rem = d >> 3;
        int co  = rem % CO;  rem /= CO;
        int rs  = rem % 9;
        int chunk = rem / 9;
        int k  = (pos & 1) ? ((pos >> 1) + 4) : (pos >> 1);
        int ci = chunk*8 + k;
        out[d] = f2tf(w[((size_t)co*CI + ci)*9 + rs]);
    }
}

// =====================================================================
// Implicit-GEMM 3x3 conv (padded tf32 input) + bias + BN + ReLU.
// Tile: M=64 output channels x N=384 pixels (4 image rows).
// 8 warps = 2(M) x 4(N rows); warp = 2 m16 x 12 n8 tiles.
// k-interleaved smem layouts -> all fragment fetches are LDS.64.
// =====================================================================
__global__ __launch_bounds__(256) void conv3x3_mma(
    const float* __restrict__ in,   // tf32 bits, padded [B, CI, 98, 98]
    const float* __restrict__ wt,   // repacked tf32 weights
    const float* __restrict__ bias, const float* __restrict__ gam,
    const float* __restrict__ bet,  const float* __restrict__ mu,
    const float* __restrict__ var,  float* __restrict__ out, // fp32 [B,CO,96,96]
    int CI, int CO)
{
    __shared__ uint32_t sW[9][64][8];     // [shift][co][kpair]   18 KB
    __shared__ uint32_t sX[6][98][8];     // [row][col][kpair]    18.4 KB

    const int tid  = threadIdx.x;
    const int warp = tid >> 5;
    const int lane = tid & 31;
    const int g    = lane >> 2;
    const int tig  = lane & 3;
    const int wm   = warp >> 2;           // 0..1
    const int wn   = warp & 3;            // 0..3

    const int y0o = blockIdx.x * 4;
    const int co0 = blockIdx.y * 64;
    const int b   = blockIdx.z;

    float acc[2][12][4];
#pragma unroll
    for (int mi = 0; mi < 2; mi++)
#pragma unroll
        for (int ni = 0; ni < 12; ni++)
#pragma unroll
            for (int q = 0; q < 4; q++) acc[mi][ni][q] = 0.f;

    const uint32_t* inb = (const uint32_t*)in + (size_t)b * CI * PPIX;
    const uint4* w4 = (const uint4*)wt;
    const int nchunks = CI >> 3;

    for (int chunk = 0; chunk < nchunks; chunk++) {
        __syncthreads();
        // weights: straight uint4 copy of [rs][64co][8] block
        {
            size_t base4 = ((size_t)(chunk*9)*CO + co0) * 2;
            for (int l = tid; l < 1152; l += 256) {
                int rs = l >> 7, t = l & 127;
                ((uint4*)sW)[l] = w4[base4 + (size_t)rs*CO*2 + t];
            }
        }
        // input: 6 padded rows x 98 cols x 8 channels, pair-interleaved
        {
            const uint32_t* cb = inb + (size_t)chunk*8*PPIX;
            for (int l = tid; l < 588; l += 256) {
                int row = l / 98, col = l % 98;
                const uint32_t* p = cb + (y0o + row)*PDIM + col;
                uint32_t x0 = p[0*PPIX], x1 = p[1*PPIX], x2 = p[2*PPIX], x3 = p[3*PPIX];
                uint32_t x4 = p[4*PPIX], x5 = p[5*PPIX], x6 = p[6*PPIX], x7 = p[7*PPIX];
                *(uint4*)&sX[row][col][0] = make_uint4(x0, x4, x1, x5);
                *(uint4*)&sX[row][col][4] = make_uint4(x2, x6, x3, x7);
            }
        }
        __syncthreads();

#pragma unroll
        for (int r = 0; r < 3; r++) {
#pragma unroll
            for (int s = 0; s < 3; s++) {
                const int rs = r*3 + s;
                const int base0 = wm*32 + g;
                uint2 va0 = *(const uint2*)&sW[rs][base0     ][tig*2];
                uint2 va1 = *(const uint2*)&sW[rs][base0 +  8][tig*2];
                uint2 va2 = *(const uint2*)&sW[rs][base0 + 16][tig*2];
                uint2 va3 = *(const uint2*)&sW[rs][base0 + 24][tig*2];
                const int prow = wn + r;
#pragma unroll
                for (int ni = 0; ni < 12; ni++) {
                    uint2 vb = *(const uint2*)&sX[prow][ni*8 + g + s][tig*2];
                    mma_tf32(acc[0][ni], va0.x, va1.x, va0.y, va1.y, vb.x, vb.y);
                    mma_tf32(acc[1][ni], va2.x, va3.x, va2.y, va3.y, vb.x, vb.y);
                }
            }
        }
    }

    // epilogue: BN + ReLU
    const int orow = y0o + wn;
#pragma unroll
    for (int mi = 0; mi < 2; mi++) {
        int c_lo = co0 + wm*32 + mi*16 + g;
        int c_hi = c_lo + 8;
        float s_lo  = gam[c_lo] * rsqrtf(var[c_lo] + 1e-5f);
        float sh_lo = (bias[c_lo] - mu[c_lo]) * s_lo + bet[c_lo];
        float s_hi  = gam[c_hi] * rsqrtf(var[c_hi] + 1e-5f);
        float sh_hi = (bias[c_hi] - mu[c_hi]) * s_hi + bet[c_hi];
        float* plo = out + (size_t)(b*CO + c_lo)*NPIX + orow*96;
        float* phi = out + (size_t)(b*CO + c_hi)*NPIX + orow*96;
#pragma unroll
        for (int ni = 0; ni < 12; ni++) {
            int x = ni*8 + tig*2;
            *(float2*)(plo + x) = make_float2(fmaxf(acc[mi][ni][0]*s_lo + sh_lo, 0.f),
                                              fmaxf(acc[mi][ni][1]*s_lo + sh_lo, 0.f));
            *(float2*)(phi + x) = make_float2(fmaxf(acc[mi][ni][2]*s_hi + sh_hi, 0.f),
                                              fmaxf(acc[mi][ni][3]*s_hi + sh_hi, 0.f));
        }
    }
}

// =====================================================================
// Pad x -> g_xp [B, 64, 98, 98], stored as tf32 bits.
// =====================================================================
__global__ __launch_bounds__(256) void pad_x_kernel(const float* __restrict__ x)
{
    const int z = blockIdx.x;
    const float* sp = x + (size_t)z * NPIX;
    float* dp = g_xp + (size_t)z * PPIX;
    for (int i = threadIdx.x; i < PPIX; i += 256) {
        int row = i / PDIM, col = i % PDIM;
        float v = 0.f;
        if (row >= 1 && row <= 96 && col >= 1 && col <= 96)
            v = sp[(row-1)*96 + (col-1)];
        dp[i] = __uint_as_float(f2tf(v));
    }
}

// =====================================================================
// Branch construction into PADDED g_tp (tf32 bits).
// =====================================================================
__global__ __launch_bounds__(256) void build_t_kernel()
{
    const int z = blockIdx.x;            // 0..767
    const int b = z / 192, c = z % 192;
    const float* yp = g_y  + (size_t)(b*192 + c) * NPIX;
    float*       tp = g_tp + (size_t)(b*192 + c) * PPIX;
    const int tid = threadIdx.x;

    if (c >= 64 && c < 128) {
        for (int i = tid; i < PPIX; i += 256) {
            int row = i / PDIM, col = i % PDIM;
            float v = 0.f;
            if (row >= 1 && row <= 96 && col >= 1 && col <= 96)
                v = yp[(row-1)*96 + (col-1)];
            tp[i] = __uint_as_float(f2tf(v));
        }
        return;
    }
    __shared__ float pool[HP*HP];
    const bool is_max = (c < 64);
    for (int idx = tid; idx < HP*HP; idx += 256) {
        int p = idx / HP, q = idx % HP;
        float a  = yp[(2*p)  *96 + 2*q    ];
        float bb = yp[(2*p)  *96 + 2*q + 1];
        float cc = yp[(2*p+1)*96 + 2*q    ];
        float dd = yp[(2*p+1)*96 + 2*q + 1];
        pool[idx] = is_max ? fmaxf(fmaxf(a,bb), fmaxf(cc,dd))
                           : 0.25f*(a + bb + cc + dd);
    }
    __syncthreads();
    for (int i = tid; i < PPIX; i += 256) {
        int row = i / PDIM, col = i % PDIM;
        if (row < 1 || row > 96 || col < 1 || col > 96) { tp[i] = 0.f; continue; }
        int h = row - 1, w = col - 1;
        float ch = fminf(fmaxf(0.5f*h - 0.25f, 0.f), 47.f);
        float cw = fminf(fmaxf(0.5f*w - 0.25f, 0.f), 47.f);
        int hlo = (int)ch; int hhi = min(hlo + 1, 47); float hf = ch - hlo;
        int wlo = (int)cw; int whi = min(wlo + 1, 47); float wf = cw - wlo;
        float top = pool[hlo*HP + wlo]*(1.f - wf) + pool[hlo*HP + whi]*wf;
        float bot = pool[hhi*HP + wlo]*(1.f - wf) + pool[hhi*HP + whi]*wf;
        tp[i] = __uint_as_float(f2tf(top*(1.f - hf) + bot*hf));
    }
}

// =====================================================================
// Row L2-norm reciprocals for q and k.
// =====================================================================
__global__ __launch_bounds__(256) void rownorm_kernel()
{
    const int x = blockIdx.x;
    const bool isK = (x >= 768);
    const int r = x % 768;
    const int b = r / 192, c = r % 192;
    const float* p = g_t2 + (size_t)(b*C1OUT + (isK ? 192 : 0) + c) * NPIX;
    const int tid = threadIdx.x;
    float s = 0.f;
    for (int i = tid; i < NPIX/4; i += 256) {
        float4 v = ((const float4*)p)[i];
        s += v.x*v.x + v.y*v.y + v.z*v.z + v.w*v.w;
    }
    __shared__ float sm[256];
    sm[tid] = s; __syncthreads();
    for (int st = 128; st > 0; st >>= 1) {
        if (tid < st) sm[tid] += sm[tid + st];
        __syncthreads();
    }
    if (tid == 0) {
        float inv = 1.f / fmaxf(sqrtf(sm[0]), 1e-12f);
        if (isK) g_kn[r] = inv; else g_qn[r] = inv;
    }
}

// =====================================================================
// QK^T via tf32 MMA. Tile 32(i) x 32(j); 8 warps split the 64-wide
// k-chunk (warp w takes k-sub w*8); partials reduced in smem.
// Epilogue folds temp * qn[i] * kn[j].
// =====================================================================
__global__ __launch_bounds__(256) void qk_mma_kernel(const float* __restrict__ temp)
{
    __shared__ __align__(16) uint8_t smraw[8*32*33*4];   // 33.8 KB, aliased
    uint32_t (*Qs)[68] = (uint32_t(*)[68])smraw;
    uint32_t (*Ks)[68] = (uint32_t(*)[68])(smraw + 32*68*4);
    float (*sP)[32][33] = (float(*)[32][33])smraw;

    const int b = blockIdx.z;
    const int i0 = blockIdx.y * 32, j0 = blockIdx.x * 32;
    const int tid  = threadIdx.x;
    const int warp = tid >> 5;
    const int lane = tid & 31;
    const int g    = lane >> 2;
    const int tig  = lane & 3;

    const float* Q = g_t2 + (size_t)b * C1OUT * NPIX;
    const float* K = Q + (size_t)192 * NPIX;

    float acc[2][4][4];
#pragma unroll
    for (int mt = 0; mt < 2; mt++)
#pragma unroll
        for (int nt = 0; nt < 4; nt++)
#pragma unroll
            for (int q = 0; q < 4; q++) acc[mt][nt][q] = 0.f;

    const int kb = warp * 8;
    for (int kt = 0; kt < NPIX; kt += 64) {
        __syncthreads();
        for (int f = tid; f < 512; f += 256) {
            int row = f >> 4, kc = (f & 15) * 4;
            float4 q4 = *(const float4*)&Q[(size_t)(i0+row)*NPIX + kt + kc];
            float4 k4 = *(const float4*)&K[(size_t)(j0+row)*NPIX + kt + kc];
            *(uint4*)&Qs[row][kc] = make_uint4(f2tf(q4.x), f2tf(q4.y), f2tf(q4.z), f2tf(q4.w));
            *(uint4*)&Ks[row][kc] = make_uint4(f2tf(k4.x), f2tf(k4.y), f2tf(k4.z), f2tf(k4.w));
        }
        __syncthreads();

        uint32_t a[2][4];
#pragma unroll
        for (int mt = 0; mt < 2; mt++) {
            int r0 = mt*16 + g;
            a[mt][0] = Qs[r0    ][kb + tig];
            a[mt][1] = Qs[r0 + 8][kb + tig];
            a[mt][2] = Qs[r0    ][kb + tig + 4];
            a[mt][3] = Qs[r0 + 8][kb + tig + 4];
        }
#pragma unroll
        for (int nt = 0; nt < 4; nt++) {
            int jr = nt*8 + g;
            uint32_t b0 = Ks[jr][kb + tig];
            uint32_t b1 = Ks[jr][kb + tig + 4];
            mma_tf32(acc[0][nt], a[0][0], a[0][1], a[0][2], a[0][3], b0, b1);
            mma_tf32(acc[1][nt], a[1][0], a[1][1], a[1][2], a[1][3], b0, b1);
        }
    }

    __syncthreads();   // done reading Qs/Ks; safe to alias as sP
#pragma unroll
    for (int mt = 0; mt < 2; mt++)
#pragma unroll
        for (int nt = 0; nt < 4; nt++) {
            int r = mt*16 + g, cix = nt*8 + tig*2;
            sP[warp][r    ][cix    ] = acc[mt][nt][0];
            sP[warp][r    ][cix + 1] = acc[mt][nt][1];
            sP[warp][r + 8][cix    ] = acc[mt][nt][2];
            sP[warp][r + 8][cix + 1] = acc[mt][nt][3];
        }
    __syncthreads();

    float tmp = temp[0];
    for (int o = tid; o < 1024; o += 256) {
        int row = o >> 5, col = o & 31;
        float s = 0.f;
#pragma unroll
        for (int w = 0; w < 8; w++) s += sP[w][row][col];
        g_att[(size_t)(b*192 + i0 + row)*192 + j0 + col] =
            s * g_qn[b*192 + i0 + row] * tmp * g_kn[b*192 + j0 + col];
    }
}

// =====================================================================
// Softmax over last dim (192).
// =====================================================================
__global__ __launch_bounds__(256) void softmax_kernel()
{
    const int row = blockIdx.x;          // 0..767
    float* p = g_att + (size_t)row * 192;
    const int t = threadIdx.x;
    __shared__ float sm[256];
    float v = (t < 192) ? p[t] : -3.0e38f;
    sm[t] = v; __syncthreads();
    for (int s = 128; s > 0; s >>= 1) {
        if (t < s) sm[t] = fmaxf(sm[t], sm[t+s]);
        __syncthreads();
    }
    float mx = sm[0]; __syncthreads();
    float e = (t < 192) ? expf(v - mx) : 0.f;
    sm[t] = e; __syncthreads();
    for (int s = 128; s > 0; s >>= 1) {
        if (t < s) sm[t] += sm[t+s];
        __syncthreads();
    }
    float inv = 1.f / sm[0];
    if (t < 192) p[t] = e * inv;
}

// =====================================================================
// O[b,i,n] = sum_j A[b,i,j] V[b,j,n]   (M=192, K=192, N=9216)
// =====================================================================
__global__ __launch_bounds__(256) void av_gemm_kernel()
{
    __shared__ float As[32][33];
    __shared__ float Vs[32][64];
    const int b = blockIdx.z;
    const int n0 = blockIdx.x * 64, i0 = blockIdx.y * 32;
    const float* A = g_att + (size_t)b * 192 * 192;
    const float* V = g_t2 + (size_t)b * C1OUT * NPIX + (size_t)384 * NPIX;
    const int tx = threadIdx.x, ty = threadIdx.y;
    const int tid = ty*16 + tx;
    float acc[2][4];
#pragma unroll
    for (int i = 0; i < 2; i++)
#pragma unroll
        for (int j = 0; j < 4; j++) acc[i][j] = 0.f;

    for (int kt = 0; kt < 192; kt += 32) {
        __syncthreads();
        for (int l = tid; l < 1024; l += 256) {
            int rr = l >> 5, cc = l & 31;
            As[cc][rr] = A[(size_t)(i0 + rr)*192 + kt + cc];
        }
        for (int l = tid; l < 512; l += 256) {
            int kk = l >> 4, nn = (l & 15) * 4;
            *(float4*)&Vs[kk][nn] = *(const float4*)&V[(size_t)(kt + kk)*NPIX + n0 + nn];
        }
        __syncthreads();
#pragma unroll
        for (int kk = 0; kk < 32; kk++) {
            float a0 = As[kk][2*ty], a1 = As[kk][2*ty+1];
            float4 vv = *(const float4*)&Vs[kk][tx*4];
            acc[0][0] += a0*vv.x; acc[0][1] += a0*vv.y;
            acc[0][2] += a0*vv.z; acc[0][3] += a0*vv.w;
            acc[1][0] += a1*vv.x; acc[1][1] += a1*vv.y;
            acc[1][2] += a1*vv.z; acc[1][3] += a1*vv.w;
        }
    }
#pragma unroll
    for (int di = 0; di < 2; di++) {
        float4 o4 = make_float4(acc[di][0], acc[di][1], acc[di][2], acc[di][3]);
        *(float4*)&g_o[(size_t)(b*192 + i0 + 2*ty + di)*NPIX + n0 + tx*4] = o4;
    }
}

// =====================================================================
// Depthwise 3x3 conv (pad 1) + bias on g_o -> d_out.
// =====================================================================
__global__ __launch_bounds__(256) void dwconv_kernel(
    const float* __restrict__ w2, const float* __restrict__ b2,
    float* __restrict__ out)
{
    __shared__ float sIn[34][34];
    const int tx = threadIdx.x, ty = threadIdx.y;
    const int tid = ty*16 + tx;
    const int z = blockIdx.z;            // 0..767
    const int b = z / 192, c = z % 192;
    const int y0 = blockIdx.y*32, x0 = blockIdx.x*32;
    const float* ip = g_o + (size_t)(b*192 + c) * NPIX;

    for (int l = tid; l < 34*34; l += 256) {
        int i = l / 34, j = l % 34;
        int gy = y0 - 1 + i, gx = x0 - 1 + j;
        float v = 0.f;
        if ((unsigned)gy < 96u && (unsigned)gx < 96u) v = ip[gy*96 + gx];
        ((float*)sIn)[l] = v;
    }
    __syncthreads();

    float wv[9];
#pragma unroll
    for (int k = 0; k < 9; k++) wv[k] = w2[c*9 + k];
    float bb = b2[c];

    float iv[4][4];
#pragma unroll
    for (int r = 0; r < 4; r++)
#pragma unroll
        for (int cc = 0; cc < 4; cc++) iv[r][cc] = sIn[2*ty + r][2*tx + cc];

    float a00 = bb, a01 = bb, a10 = bb, a11 = bb;
#pragma unroll
    for (int ky = 0; ky < 3; ky++)
#pragma unroll
        for (int kx = 0; kx < 3; kx++) {
            float wk = wv[ky*3 + kx];
            a00 += iv[ky  ][kx  ]*wk;
            a01 += iv[ky  ][kx+1]*wk;
            a10 += iv[ky+1][kx  ]*wk;
            a11 += iv[ky+1][kx+1]*wk;
        }
    const int oy = y0 + 2*ty, ox = x0 + 2*tx;
    float* op = out + (size_t)(b*192 + c)*NPIX + oy*96 + ox;
    op[0] = a00; op[1] = a01; op[96] = a10; op[97] = a11;
}

// =====================================================================
// Launcher
// =====================================================================
extern "C" void kernel_launch(void* const* d_in, const int* in_sizes, int n_in,
                              void* d_out, int out_size)
{
    const float* x    = (const float*)d_in[0];
    const float* w0   = (const float*)d_in[1];
    const float* b0   = (const float*)d_in[2];
    const float* g0   = (const float*)d_in[3];
    const float* be0  = (const float*)d_in[4];
    const float* m0   = (const float*)d_in[5];
    const float* v0   = (const float*)d_in[6];
    const float* w1   = (const float*)d_in[7];
    const float* b1   = (const float*)d_in[8];
    const float* g1   = (const float*)d_in[9];
    const float* be1  = (const float*)d_in[10];
    const float* m1   = (const float*)d_in[11];
    const float* v1   = (const float*)d_in[12];
    const float* temp = (const float*)d_in[13];
    const float* w2   = (const float*)d_in[14];
    const float* b2   = (const float*)d_in[15];
    float* out = (float*)d_out;

    float *pxp, *py, *ptp, *pt2, *pw0t, *pw1t;
    cudaGetSymbolAddress((void**)&pxp,  g_xp);
    cudaGetSymbolAddress((void**)&py,   g_y);
    cudaGetSymbolAddress((void**)&ptp,  g_tp);
    cudaGetSymbolAddress((void**)&pt2,  g_t2);
    cudaGetSymbolAddress((void**)&pw0t, g_w0t);
    cudaGetSymbolAddress((void**)&pw1t, g_w1t);

    // weight repacks (tf32, mma-friendly layout)
    repack_w_kernel<<<432, 256>>>(w0, pw0t, C0IN, C0OUT);
    repack_w_kernel<<<1024, 256>>>(w1, pw1t, C0OUT, C1OUT);

    // pad x -> g_xp (tf32)
    pad_x_kernel<<<B4*C0IN, 256>>>(x);

    // conv0 + bn + relu : g_xp -> g_y
    conv3x3_mma<<<dim3(24, C0OUT/64, B4), 256>>>(
        pxp, pw0t, b0, g0, be0, m0, v0, py, C0IN, C0OUT);

    // branches -> padded g_tp (tf32)
    build_t_kernel<<<B4*192, 256>>>();

    // conv1 + bn + relu : g_tp -> g_t2
    conv3x3_mma<<<dim3(24, C1OUT/64, B4), 256>>>(
        ptp, pw1t, b1, g1, be1, m1, v1, pt2, C0OUT, C1OUT);

    // q/k row norms
    rownorm_kernel<<<2*B4*192, 256>>>();

    // attention logits (tensor cores)
    qk_mma_kernel<<<dim3(6, 6, B4), 256>>>(temp);

    // softmax
    softmax_kernel<<<B4*192, 256>>>();

    // attn @ v
    av_gemm_kernel<<<dim3(144, 6, B4), dim3(16,16)>>>();

    // depthwise conv + bias -> output
    dwconv_kernel<<<dim3(3, 3, B4*192), dim3(16,16)>>>(w2, b2, out);
}

// round 7
// speedup vs baseline: 8.5024x; 1.1706x over previous
#include <cuda_runtime.h>
#include <math.h>
#include <stdint.h>

// ---------------- problem constants ----------------
#define B4    4
#define C0IN  64
#define C0OUT 192
#define C1OUT 576
#define NPIX  (96*96)          // 9216
#define PDIM  98
#define PPIX  (98*98)          // 9604
#define HP    48               // pooled size

// ---------------- scratch (device globals; no allocation allowed) ----------
__device__ float g_xp [B4*C0IN *PPIX];   // padded x, chunked channel-last-8, tf32 bits
__device__ float g_y  [B4*C0OUT*NPIX];   // after conv0+bn+relu (fp32)
__device__ float g_tp [B4*C0OUT*PPIX];   // padded branch concat, chunked, tf32 bits
__device__ float g_t2 [B4*C1OUT*NPIX];   // after conv1+bn+relu (fp32)
__device__ float g_att[B4*192*192];      // attention logits / probs
__device__ float g_o  [B4*C0OUT*NPIX];   // attn @ v
__device__ float g_qn [B4*192];          // 1/||q||
__device__ float g_kn [B4*192];          // 1/||k||
__device__ float g_w0t[C0OUT*C0IN*9];    // repacked tf32 weights conv0
__device__ float g_w1t[C1OUT*C0OUT*9];   // repacked tf32 weights conv1

// ---------------- helpers ----------------
__device__ __forceinline__ uint32_t f2tf(float f) {
    uint32_t r;
    asm("cvt.rna.tf32.f32 %0, %1;" : "=r"(r) : "f"(f));
    return r;
}
__device__ __forceinline__ void mma_tf32(float c[4],
    uint32_t a0, uint32_t a1, uint32_t a2, uint32_t a3,
    uint32_t b0, uint32_t b1)
{
    asm volatile(
        "mma.sync.aligned.m16n8k8.row.col.f32.tf32.tf32.f32 "
        "{%0,%1,%2,%3}, {%4,%5,%6,%7}, {%8,%9}, {%0,%1,%2,%3};"
        : "+f"(c[0]), "+f"(c[1]), "+f"(c[2]), "+f"(c[3])
        : "r"(a0), "r"(a1), "r"(a2), "r"(a3), "r"(b0), "r"(b1));
}
__device__ __forceinline__ void cp16(void* s, const void* g) {
    uint32_t sa = (uint32_t)__cvta_generic_to_shared(s);
    asm volatile("cp.async.cg.shared.global [%0], [%1], 16;" :: "r"(sa), "l"(g));
}
// pos(k) = (k&3)*2 + (k>>2)  /  k(pos) = (pos>>1) + ((pos&1)<<2)

// =====================================================================
// Weight repack: w[CO,CI,3,3] fp32 -> tf32 bits,
// out[((chunk*9 + rs)*CO + co)*8 + pos]
// =====================================================================
__global__ __launch_bounds__(256) void repack_w_kernel(
    const float* __restrict__ w, float* __restrict__ outf, int CI, int CO)
{
    uint32_t* out = (uint32_t*)outf;
    const int total = CO * CI * 9;
    for (int d = blockIdx.x*256 + threadIdx.x; d < total; d += gridDim.x*256) {
        int pos = d & 7;
        int rem = d >> 3;
        int co  = rem % CO;  rem /= CO;
        int rs  = rem % 9;
        int chunk = rem / 9;
        int k  = (pos >> 1) + ((pos & 1) << 2);
        int ci = chunk*8 + k;
        out[d] = f2tf(w[((size_t)co*CI + ci)*9 + rs]);
    }
}

// =====================================================================
// Implicit-GEMM 3x3 conv + bias + BN + ReLU, tf32 MMA,
// cp.async double-buffered, channel-last-8 input layout.
// Tile: M=64 out-channels x N=384 pixels (4 rows). 8 warps = 2(M) x 4(rows).
// =====================================================================
#define SW_BYTES 18432   // 9*64*8*4
#define SX_BYTES 18816   // 6*98*8*4
#define CONV_SMEM (2*SW_BYTES + 2*SX_BYTES)   // 74496

__global__ __launch_bounds__(256, 2) void conv3x3_mma(
    const float* __restrict__ in,   // tf32 bits, [B][CI/8][98][98][8]
    const float* __restrict__ wt,   // repacked tf32 weights
    const float* __restrict__ bias, const float* __restrict__ gam,
    const float* __restrict__ bet,  const float* __restrict__ mu,
    const float* __restrict__ var,  float* __restrict__ out, // fp32 [B,CO,96,96]
    int CI, int CO)
{
    extern __shared__ uint8_t dynsm[];

    const int tid  = threadIdx.x;
    const int warp = tid >> 5;
    const int lane = tid & 31;
    const int g    = lane >> 2;
    const int tig  = lane & 3;
    const int wm   = warp >> 2;           // 0..1
    const int wn   = warp & 3;            // 0..3

    const int y0o = blockIdx.x * 4;
    const int co0 = blockIdx.y * 64;
    const int b   = blockIdx.z;
    const int nchunks = CI >> 3;

    const uint4* w4 = (const uint4*)wt;

    float acc[2][12][4];
#pragma unroll
    for (int mi = 0; mi < 2; mi++)
#pragma unroll
        for (int ni = 0; ni < 12; ni++)
#pragma unroll
            for (int q = 0; q < 4; q++) acc[mi][ni][q] = 0.f;

    // async loader for one chunk into stage stg
    auto load_chunk = [&](int chunk, int stg) {
        uint4* wdst = (uint4*)(dynsm + stg*SW_BYTES);
        const uint4* wsrc = w4 + ((size_t)chunk*9*CO + co0)*2;
        for (int l = tid; l < 1152; l += 256) {
            int rs = l >> 7, t = l & 127;
            cp16(wdst + l, wsrc + (size_t)rs*CO*2 + t);
        }
        uint4* xdst = (uint4*)(dynsm + 2*SW_BYTES + stg*SX_BYTES);
        const uint4* xsrc = (const uint4*)in +
            (((size_t)(b*nchunks + chunk))*PPIX + (size_t)y0o*98)*2;
        for (int l = tid; l < 1176; l += 256)
            cp16(xdst + l, xsrc + l);
    };

    load_chunk(0, 0);
    asm volatile("cp.async.commit_group;" ::: "memory");

    for (int chunk = 0; chunk < nchunks; chunk++) {
        const int st = chunk & 1;
        const bool more = (chunk + 1 < nchunks);
        if (more) {
            load_chunk(chunk + 1, st ^ 1);
            asm volatile("cp.async.commit_group;" ::: "memory");
            asm volatile("cp.async.wait_group 1;" ::: "memory");
        } else {
            asm volatile("cp.async.wait_group 0;" ::: "memory");
        }
        __syncthreads();

        const uint32_t (*W8)[64][8] = (const uint32_t (*)[64][8])(dynsm + st*SW_BYTES);
        const uint32_t (*X8)[98][8] = (const uint32_t (*)[98][8])(dynsm + 2*SW_BYTES + st*SX_BYTES);

#pragma unroll
        for (int r = 0; r < 3; r++) {
#pragma unroll
            for (int s = 0; s < 3; s++) {
                const int rs = r*3 + s;
                const int base0 = wm*32 + g;
                uint2 va0 = *(const uint2*)&W8[rs][base0     ][tig*2];
                uint2 va1 = *(const uint2*)&W8[rs][base0 +  8][tig*2];
                uint2 va2 = *(const uint2*)&W8[rs][base0 + 16][tig*2];
                uint2 va3 = *(const uint2*)&W8[rs][base0 + 24][tig*2];
                const int prow = wn + r;
#pragma unroll
                for (int ni = 0; ni < 12; ni++) {
                    uint2 vb = *(const uint2*)&X8[prow][ni*8 + g + s][tig*2];
                    mma_tf32(acc[0][ni], va0.x, va1.x, va0.y, va1.y, vb.x, vb.y);
                    mma_tf32(acc[1][ni], va2.x, va3.x, va2.y, va3.y, vb.x, vb.y);
                }
            }
        }
        __syncthreads();
    }

    // epilogue: BN + ReLU
    const int orow = y0o + wn;
#pragma unroll
    for (int mi = 0; mi < 2; mi++) {
        int c_lo = co0 + wm*32 + mi*16 + g;
        int c_hi = c_lo + 8;
        float s_lo  = gam[c_lo] * rsqrtf(var[c_lo] + 1e-5f);
        float sh_lo = (bias[c_lo] - mu[c_lo]) * s_lo + bet[c_lo];
        float s_hi  = gam[c_hi] * rsqrtf(var[c_hi] + 1e-5f);
        float sh_hi = (bias[c_hi] - mu[c_hi]) * s_hi + bet[c_hi];
        float* plo = out + (size_t)(b*CO + c_lo)*NPIX + orow*96;
        float* phi = out + (size_t)(b*CO + c_hi)*NPIX + orow*96;
#pragma unroll
        for (int ni = 0; ni < 12; ni++) {
            int x = ni*8 + tig*2;
            *(float2*)(plo + x) = make_float2(fmaxf(acc[mi][ni][0]*s_lo + sh_lo, 0.f),
                                              fmaxf(acc[mi][ni][1]*s_lo + sh_lo, 0.f));
            *(float2*)(phi + x) = make_float2(fmaxf(acc[mi][ni][2]*s_hi + sh_hi, 0.f),
                                              fmaxf(acc[mi][ni][3]*s_hi + sh_hi, 0.f));
        }
    }
}

// =====================================================================
// Pad x -> g_xp [B][8][98][98][8] tf32 bits.
// grid = B4*8*7 (7 row-bands of 14 rows).
// =====================================================================
__global__ __launch_bounds__(256) void pad_x_kernel(const float* __restrict__ x)
{
    const int z = blockIdx.x;
    const int band  = z % 7;
    const int chunk = (z / 7) & 7;
    const int b     = z / 56;
    float* dp = g_xp + ((size_t)(b*8 + chunk))*PPIX*8;
    const float* sp = x + ((size_t)b*C0IN + chunk*8)*NPIX;
    for (int i = threadIdx.x; i < 14*98*8; i += 256) {
        int pos = i & 7;
        int p   = i >> 3;
        int lrow = p / 98, col = p % 98;
        int row = band*14 + lrow;
        int k = (pos >> 1) + ((pos & 1) << 2);
        float v = 0.f;
        if (row >= 1 && row <= 96 && col >= 1 && col <= 96)
            v = sp[(size_t)k*NPIX + (row-1)*96 + (col-1)];
        dp[((size_t)row*98 + col)*8 + pos] = __uint_as_float(f2tf(v));
    }
}

// =====================================================================
// Branch construction into g_tp [B][24][98][98][8] tf32 bits.
// chunks 0-7: bilinear(maxpool2); 8-15: copy; 16-23: bilinear(avgpool2).
// One block (1024 thr) per (b, chunk); pooled planes in dynamic smem.
// =====================================================================
#define POOLPAD (HP*HP + 1)
#define BUILD_SMEM (8*POOLPAD*4)    // 73760 B

__global__ __launch_bounds__(1024) void build_t_kernel()
{
    extern __shared__ float pool[];   // [8][POOLPAD]
    const int z = blockIdx.x;         // 0..95
    const int b = z / 24, chunk = z % 24;
    const int tid = threadIdx.x;
    float* dp = g_tp + ((size_t)z)*PPIX*8;
    const float* yb = g_y + ((size_t)b*192)*NPIX;

    if (chunk >= 8 && chunk < 16) {
        for (int i = tid; i < PPIX*8; i += 1024) {
            int pos = i & 7;
            int p = i >> 3;
            int row = p / 98, col = p % 98;
            int k = (pos >> 1) + ((pos & 1) << 2);
            int c = chunk*8 + k;
            float v = 0.f;
            if (row >= 1 && row <= 96 && col >= 1 && col <= 96)
                v = yb[(size_t)c*NPIX + (row-1)*96 + (col-1)];
            dp[i] = __uint_as_float(f2tf(v));
        }
        return;
    }

    const bool is_max = (chunk < 8);
    for (int i = tid; i < 8*HP*HP; i += 1024) {
        int k = i / (HP*HP);
        int idx = i % (HP*HP);
        int p = idx / HP, q = idx % HP;
        int c = chunk*8 + k;
        const float* yp = yb + (size_t)c*NPIX;
        float a  = yp[(2*p)  *96 + 2*q    ];
        float bb = yp[(2*p)  *96 + 2*q + 1];
        float cc = yp[(2*p+1)*96 + 2*q    ];
        float dd = yp[(2*p+1)*96 + 2*q + 1];
        int pos = (k & 3)*2 + (k >> 2);
        pool[pos*POOLPAD + idx] = is_max ? fmaxf(fmaxf(a,bb), fmaxf(cc,dd))
                                         : 0.25f*(a + bb + cc + dd);
    }
    __syncthreads();

    for (int i = tid; i < PPIX*8; i += 1024) {
        int pos = i & 7;
        int p = i >> 3;
        int row = p / 98, col = p % 98;
        float o = 0.f;
        if (row >= 1 && row <= 96 && col >= 1 && col <= 96) {
            int h = row - 1, w = col - 1;
            float chf = fminf(fmaxf(0.5f*h - 0.25f, 0.f), 47.f);
            float cwf = fminf(fmaxf(0.5f*w - 0.25f, 0.f), 47.f);
            int hlo = (int)chf; int hhi = min(hlo + 1, 47); float hf = chf - hlo;
            int wlo = (int)cwf; int whi = min(wlo + 1, 47); float wf = cwf - wlo;
            const float* pl = pool + pos*POOLPAD;
            float top = pl[hlo*HP + wlo]*(1.f - wf) + pl[hlo*HP + whi]*wf;
            float bot = pl[hhi*HP + wlo]*(1.f - wf) + pl[hhi*HP + whi]*wf;
            o = top*(1.f - hf) + bot*hf;
        }
        dp[i] = __uint_as_float(f2tf(o));
    }
}

// =====================================================================
// Row L2-norm reciprocals for q and k.
// =====================================================================
__global__ __launch_bounds__(256) void rownorm_kernel()
{
    const int x = blockIdx.x;
    const bool isK = (x >= 768);
    const int r = x % 768;
    const int b = r / 192, c = r % 192;
    const float* p = g_t2 + (size_t)(b*C1OUT + (isK ? 192 : 0) + c) * NPIX;
    const int tid = threadIdx.x;
    float s = 0.f;
    for (int i = tid; i < NPIX/4; i += 256) {
        float4 v = ((const float4*)p)[i];
        s += v.x*v.x + v.y*v.y + v.z*v.z + v.w*v.w;
    }
    __shared__ float sm[256];
    sm[tid] = s; __syncthreads();
    for (int st = 128; st > 0; st >>= 1) {
        if (tid < st) sm[tid] += sm[tid + st];
        __syncthreads();
    }
    if (tid == 0) {
        float inv = 1.f / fmaxf(sqrtf(sm[0]), 1e-12f);
        if (isK) g_kn[r] = inv; else g_qn[r] = inv;
    }
}

// =====================================================================
// QK^T via tf32 MMA (split-k over 8 warps, smem reduce).
// =====================================================================
__global__ __launch_bounds__(256) void qk_mma_kernel(const float* __restrict__ temp)
{
    __shared__ __align__(16) uint8_t smraw[8*32*33*4];
    uint32_t (*Qs)[68] = (uint32_t(*)[68])smraw;
    uint32_t (*Ks)[68] = (uint32_t(*)[68])(smraw + 32*68*4);
    float (*sP)[32][33] = (float(*)[32][33])smraw;

    const int b = blockIdx.z;
    const int i0 = blockIdx.y * 32, j0 = blockIdx.x * 32;
    const int tid  = threadIdx.x;
    const int warp = tid >> 5;
    const int lane = tid & 31;
    const int g    = lane >> 2;
    const int tig  = lane & 3;

    const float* Q = g_t2 + (size_t)b * C1OUT * NPIX;
    const float* K = Q + (size_t)192 * NPIX;

    float acc[2][4][4];
#pragma unroll
    for (int mt = 0; mt < 2; mt++)
#pragma unroll
        for (int nt = 0; nt < 4; nt++)
#pragma unroll
            for (int q = 0; q < 4; q++) acc[mt][nt][q] = 0.f;

    const int kb = warp * 8;
    for (int kt = 0; kt < NPIX; kt += 64) {
        __syncthreads();
        for (int f = tid; f < 512; f += 256) {
            int row = f >> 4, kc = (f & 15) * 4;
            float4 q4 = *(const float4*)&Q[(size_t)(i0+row)*NPIX + kt + kc];
            float4 k4 = *(const float4*)&K[(size_t)(j0+row)*NPIX + kt + kc];
            *(uint4*)&Qs[row][kc] = make_uint4(f2tf(q4.x), f2tf(q4.y), f2tf(q4.z), f2tf(q4.w));
            *(uint4*)&Ks[row][kc] = make_uint4(f2tf(k4.x), f2tf(k4.y), f2tf(k4.z), f2tf(k4.w));
        }
        __syncthreads();

        uint32_t a[2][4];
#pragma unroll
        for (int mt = 0; mt < 2; mt++) {
            int r0 = mt*16 + g;
            a[mt][0] = Qs[r0    ][kb + tig];
            a[mt][1] = Qs[r0 + 8][kb + tig];
            a[mt][2] = Qs[r0    ][kb + tig + 4];
            a[mt][3] = Qs[r0 + 8][kb + tig + 4];
        }
#pragma unroll
        for (int nt = 0; nt < 4; nt++) {
            int jr = nt*8 + g;
            uint32_t b0 = Ks[jr][kb + tig];
            uint32_t b1 = Ks[jr][kb + tig + 4];
            mma_tf32(acc[0][nt], a[0][0], a[0][1], a[0][2], a[0][3], b0, b1);
            mma_tf32(acc[1][nt], a[1][0], a[1][1], a[1][2], a[1][3], b0, b1);
        }
    }

    __syncthreads();
#pragma unroll
    for (int mt = 0; mt < 2; mt++)
#pragma unroll
        for (int nt = 0; nt < 4; nt++) {
            int r = mt*16 + g, cix = nt*8 + tig*2;
            sP[warp][r    ][cix    ] = acc[mt][nt][0];
            sP[warp][r    ][cix + 1] = acc[mt][nt][1];
            sP[warp][r + 8][cix    ] = acc[mt][nt][2];
            sP[warp][r + 8][cix + 1] = acc[mt][nt][3];
        }
    __syncthreads();

    float tmp = temp[0];
    for (int o = tid; o < 1024; o += 256) {
        int row = o >> 5, col = o & 31;
        float s = 0.f;
#pragma unroll
        for (int w = 0; w < 8; w++) s += sP[w][row][col];
        g_att[(size_t)(b*192 + i0 + row)*192 + j0 + col] =
            s * g_qn[b*192 + i0 + row] * tmp * g_kn[b*192 + j0 + col];
    }
}

// =====================================================================
// Softmax over last dim (192).
// =====================================================================
__global__ __launch_bounds__(256) void softmax_kernel()
{
    const int row = blockIdx.x;          // 0..767
    float* p = g_att + (size_t)row * 192;
    const int t = threadIdx.x;
    __shared__ float sm[256];
    float v = (t < 192) ? p[t] : -3.0e38f;
    sm[t] = v; __syncthreads();
    for (int s = 128; s > 0; s >>= 1) {
        if (t < s) sm[t] = fmaxf(sm[t], sm[t+s]);
        __syncthreads();
    }
    float mx = sm[0]; __syncthreads();
    float e = (t < 192) ? expf(v - mx) : 0.f;
    sm[t] = e; __syncthreads();
    for (int s = 128; s > 0; s >>= 1) {
        if (t < s) sm[t] += sm[t+s];
        __syncthreads();
    }
    float inv = 1.f / sm[0];
    if (t < 192) p[t] = e * inv;
}

// =====================================================================
// O = A @ V via tf32 MMA. CTA tile 32(i) x 128(n); K=192 (j), chunk 32.
// 8 warps each own 16 n-columns. A tile loaded once.
// =====================================================================
__global__ __launch_bounds__(256) void av_mma_kernel()
{
    __shared__ uint32_t As[32][196];     // 32 rows x 192 k (pad 196)  25.1 KB
    __shared__ uint32_t Vs[128][36];     // 128 n x 32 k (pad 36)      18.4 KB

    const int b  = blockIdx.z;
    const int i0 = blockIdx.y * 32;
    const int n0 = blockIdx.x * 128;
    const int tid  = threadIdx.x;
    const int warp = tid >> 5;
    const int lane = tid & 31;
    const int g    = lane >> 2;
    const int tig  = lane & 3;

    const float* A = g_att + (size_t)b * 192 * 192;
    const float* V = g_t2 + ((size_t)b*C1OUT + 384) * NPIX;

    // load + convert the whole A tile once
#pragma unroll
    for (int j = 0; j < 24; j++) {
        int l = j*256 + tid;
        int r = l / 192, c = l % 192;
        As[r][c] = f2tf(A[(size_t)(i0 + r)*192 + c]);
    }

    float acc[2][2][4];
#pragma unroll
    for (int mt = 0; mt < 2; mt++)
#pragma unroll
        for (int nt = 0; nt < 2; nt++)
#pragma unroll
            for (int q = 0; q < 4; q++) acc[mt][nt][q] = 0.f;

    for (int kt = 0; kt < 192; kt += 32) {
        __syncthreads();
        for (int l = tid; l < 4096; l += 256) {
            int kk = l >> 7, nn = l & 127;
            Vs[nn][kk] = f2tf(V[(size_t)(kt + kk)*NPIX + n0 + nn]);
        }
        __syncthreads();

#pragma unroll
        for (int ks = 0; ks < 4; ks++) {
            const int ka = kt + ks*8;
            uint32_t a[2][4];
#pragma unroll
            for (int mt = 0; mt < 2; mt++) {
                int r0 = mt*16 + g;
                a[mt][0] = As[r0    ][ka + tig];
                a[mt][1] = As[r0 + 8][ka + tig];
                a[mt][2] = As[r0    ][ka + tig + 4];
                a[mt][3] = As[r0 + 8][ka + tig + 4];
            }
#pragma unroll
            for (int nt = 0; nt < 2; nt++) {
                int nr = warp*16 + nt*8 + g;
                uint32_t b0 = Vs[nr][ks*8 + tig];
                uint32_t b1 = Vs[nr][ks*8 + tig + 4];
                mma_tf32(acc[0][nt], a[0][0], a[0][1], a[0][2], a[0][3], b0, b1);
                mma_tf32(acc[1][nt], a[1][0], a[1][1], a[1][2], a[1][3], b0, b1);
            }
        }
    }

    // epilogue
#pragma unroll
    for (int mt = 0; mt < 2; mt++) {
        int r = i0 + mt*16 + g;
#pragma unroll
        for (int nt = 0; nt < 2; nt++) {
            int nc = n0 + warp*16 + nt*8 + tig*2;
            *(float2*)&g_o[((size_t)(b*192) + r    )*NPIX + nc] =
                make_float2(acc[mt][nt][0], acc[mt][nt][1]);
            *(float2*)&g_o[((size_t)(b*192) + r + 8)*NPIX + nc] =
                make_float2(acc[mt][nt][2], acc[mt][nt][3]);
        }
    }
}

// =====================================================================
// Depthwise 3x3 conv (pad 1) + bias on g_o -> d_out.
// =====================================================================
__global__ __launch_bounds__(256) void dwconv_kernel(
    const float* __restrict__ w2, const float* __restrict__ b2,
    float* __restrict__ out)
{
    __shared__ float sIn[34][34];
    const int tx = threadIdx.x, ty = threadIdx.y;
    const int tid = ty*16 + tx;
    const int z = blockIdx.z;            // 0..767
    const int b = z / 192, c = z % 192;
    const int y0 = blockIdx.y*32, x0 = blockIdx.x*32;
    const float* ip = g_o + (size_t)(b*192 + c) * NPIX;

    for (int l = tid; l < 34*34; l += 256) {
        int i = l / 34, j = l % 34;
        int gy = y0 - 1 + i, gx = x0 - 1 + j;
        float v = 0.f;
        if ((unsigned)gy < 96u && (unsigned)gx < 96u) v = ip[gy*96 + gx];
        ((float*)sIn)[l] = v;
    }
    __syncthreads();

    float wv[9];
#pragma unroll
    for (int k = 0; k < 9; k++) wv[k] = w2[c*9 + k];
    float bb = b2[c];

    float iv[4][4];
#pragma unroll
    for (int r = 0; r < 4; r++)
#pragma unroll
        for (int cc = 0; cc < 4; cc++) iv[r][cc] = sIn[2*ty + r][2*tx + cc];

    float a00 = bb, a01 = bb, a10 = bb, a11 = bb;
#pragma unroll
    for (int ky = 0; ky < 3; ky++)
#pragma unroll
        for (int kx = 0; kx < 3; kx++) {
            float wk = wv[ky*3 + kx];
            a00 += iv[ky  ][kx  ]*wk;
            a01 += iv[ky  ][kx+1]*wk;
            a10 += iv[ky+1][kx  ]*wk;
            a11 += iv[ky+1][kx+1]*wk;
        }
    const int oy = y0 + 2*ty, ox = x0 + 2*tx;
    float* op = out + (size_t)(b*192 + c)*NPIX + oy*96 + ox;
    op[0] = a00; op[1] = a01; op[96] = a10; op[97] = a11;
}

// =====================================================================
// Launcher
// =====================================================================
extern "C" void kernel_launch(void* const* d_in, const int* in_sizes, int n_in,
                              void* d_out, int out_size)
{
    const float* x    = (const float*)d_in[0];
    const float* w0   = (const float*)d_in[1];
    const float* b0   = (const float*)d_in[2];
    const float* g0   = (const float*)d_in[3];
    const float* be0  = (const float*)d_in[4];
    const float* m0   = (const float*)d_in[5];
    const float* v0   = (const float*)d_in[6];
    const float* w1   = (const float*)d_in[7];
    const float* b1   = (const float*)d_in[8];
    const float* g1   = (const float*)d_in[9];
    const float* be1  = (const float*)d_in[10];
    const float* m1   = (const float*)d_in[11];
    const float* v1   = (const float*)d_in[12];
    const float* temp = (const float*)d_in[13];
    const float* w2   = (const float*)d_in[14];
    const float* b2   = (const float*)d_in[15];
    float* out = (float*)d_out;

    float *pxp, *py, *ptp, *pt2, *pw0t, *pw1t;
    cudaGetSymbolAddress((void**)&pxp,  g_xp);
    cudaGetSymbolAddress((void**)&py,   g_y);
    cudaGetSymbolAddress((void**)&ptp,  g_tp);
    cudaGetSymbolAddress((void**)&pt2,  g_t2);
    cudaGetSymbolAddress((void**)&pw0t, g_w0t);
    cudaGetSymbolAddress((void**)&pw1t, g_w1t);

    cudaFuncSetAttribute(conv3x3_mma,
        cudaFuncAttributeMaxDynamicSharedMemorySize, CONV_SMEM);
    cudaFuncSetAttribute(build_t_kernel,
        cudaFuncAttributeMaxDynamicSharedMemorySize, BUILD_SMEM);

    // weight repacks (tf32, mma-friendly layout)
    repack_w_kernel<<<432, 256>>>(w0, pw0t, C0IN, C0OUT);
    repack_w_kernel<<<1024, 256>>>(w1, pw1t, C0OUT, C1OUT);

    // pad x -> g_xp (tf32, chunked channel-last-8)
    pad_x_kernel<<<B4*8*7, 256>>>(x);

    // conv0 + bn + relu : g_xp -> g_y
    conv3x3_mma<<<dim3(24, C0OUT/64, B4), 256, CONV_SMEM>>>(
        pxp, pw0t, b0, g0, be0, m0, v0, py, C0IN, C0OUT);

    // branches -> g_tp (tf32, chunked)
    build_t_kernel<<<B4*24, 1024, BUILD_SMEM>>>();

    // conv1 + bn + relu : g_tp -> g_t2
    conv3x3_mma<<<dim3(24, C1OUT/64, B4), 256, CONV_SMEM>>>(
        ptp, pw1t, b1, g1, be1, m1, v1, pt2, C0OUT, C1OUT);

    // q/k row norms
    rownorm_kernel<<<2*B4*192, 256>>>();

    // attention logits (tensor cores)
    qk_mma_kernel<<<dim3(6, 6, B4), 256>>>(temp);

    // softmax
    softmax_kernel<<<B4*192, 256>>>();

    // attn @ v (tensor cores)
    av_mma_kernel<<<dim3(72, 6, B4), 256>>>();

    // depthwise conv + bias -> output
    dwconv_kernel<<<dim3(3, 3, B4*192), dim3(16,16)>>>(w2, b2, out);
}

// round 8
// speedup vs baseline: 11.7480x; 1.3817x over previous
#include <cuda_runtime.h>
#include <cuda_bf16.h>
#include <math.h>
#include <stdint.h>

// ---------------- problem constants ----------------
#define B4    4
#define C0IN  64
#define C0OUT 192
#define C1OUT 576
#define NPIX  (96*96)          // 9216
#define PDIM  98
#define PPIX  (98*98)          // 9604
#define HP    48               // pooled size

// ---------------- scratch (device globals; no allocation allowed) ----------
// (float-typed for sizing; conv path reinterprets as packed bf16 words)
__device__ float g_xp [B4*C0IN*PPIX];    // padded x, [B][4][98][98][8w] bf16x2
__device__ float g_y  [B4*C0OUT*NPIX];   // after conv0+bn+relu (fp32)
__device__ float g_tp [B4*C0OUT*PPIX];   // padded concat, [B][12][98][98][8w] bf16x2
__device__ float g_t2 [B4*C1OUT*NPIX];   // after conv1+bn+relu (fp32)
__device__ float g_att[B4*192*192];      // attention logits / probs
__device__ float g_o  [B4*C0OUT*NPIX];   // attn @ v
__device__ float g_qn [B4*192];          // 1/||q||
__device__ float g_kn [B4*192];          // 1/||k||
__device__ float g_w0t[C0OUT*C0IN*9];    // repacked bf16 weights conv0 (oversized)
__device__ float g_w1t[C1OUT*C0OUT*9];   // repacked bf16 weights conv1 (oversized)

// ---------------- helpers ----------------
__device__ __forceinline__ uint32_t f2tf(float f) {
    uint32_t r;
    asm("cvt.rna.tf32.f32 %0, %1;" : "=r"(r) : "f"(f));
    return r;
}
__device__ __forceinline__ uint32_t pack_bf16(float lo, float hi) {
    __nv_bfloat162 v = __floats2bfloat162_rn(lo, hi);   // .x = lo halfword
    return *(uint32_t*)&v;
}
__device__ __forceinline__ void mma_tf32(float c[4],
    uint32_t a0, uint32_t a1, uint32_t a2, uint32_t a3,
    uint32_t b0, uint32_t b1)
{
    asm volatile(
        "mma.sync.aligned.m16n8k8.row.col.f32.tf32.tf32.f32 "
        "{%0,%1,%2,%3}, {%4,%5,%6,%7}, {%8,%9}, {%0,%1,%2,%3};"
        : "+f"(c[0]), "+f"(c[1]), "+f"(c[2]), "+f"(c[3])
        : "r"(a0), "r"(a1), "r"(a2), "r"(a3), "r"(b0), "r"(b1));
}
__device__ __forceinline__ void mma_bf16(float c[4],
    uint32_t a0, uint32_t a1, uint32_t a2, uint32_t a3,
    uint32_t b0, uint32_t b1)
{
    asm volatile(
        "mma.sync.aligned.m16n8k16.row.col.f32.bf16.bf16.f32 "
        "{%0,%1,%2,%3}, {%4,%5,%6,%7}, {%8,%9}, {%0,%1,%2,%3};"
        : "+f"(c[0]), "+f"(c[1]), "+f"(c[2]), "+f"(c[3])
        : "r"(a0), "r"(a1), "r"(a2), "r"(a3), "r"(b0), "r"(b1));
}
__device__ __forceinline__ void cp16(void* s, const void* g) {
    uint32_t sa = (uint32_t)__cvta_generic_to_shared(s);
    asm volatile("cp.async.cg.shared.global [%0], [%1], 16;" :: "r"(sa), "l"(g));
}
// word layout (16 ch -> 8 uint32 words): word j holds channel pair pc where
//   j = (pc & 3)*2 + (pc >> 2), i.e. pairs (2t,2t+1) and (2t+8,2t+9) are
//   adjacent words -> one LDS.64 per MMA fragment.
// inverse: pc = (j >> 1) + ((j & 1) << 2); channels = 2*pc, 2*pc+1.

// =====================================================================
// Weight repack: w[CO,CI,3,3] fp32 -> bf16 words,
// out[((chunk*9 + rs)*CO + co)*8 + j]
// =====================================================================
__global__ __launch_bounds__(256) void repack_w_kernel(
    const float* __restrict__ w, float* __restrict__ outf, int CI, int CO)
{
    uint32_t* out = (uint32_t*)outf;
    const int total = CO * (CI >> 4) * 9 * 8;
    for (int d = blockIdx.x*256 + threadIdx.x; d < total; d += gridDim.x*256) {
        int j   = d & 7;
        int rem = d >> 3;
        int co  = rem % CO;  rem /= CO;
        int rs  = rem % 9;
        int chunk = rem / 9;
        int pc = (j >> 1) + ((j & 1) << 2);
        int c_lo = chunk*16 + pc*2;
        out[d] = pack_bf16(w[((size_t)co*CI + c_lo    )*9 + rs],
                           w[((size_t)co*CI + c_lo + 1)*9 + rs]);
    }
}

// =====================================================================
// Implicit-GEMM 3x3 conv + bias + BN + ReLU, bf16 m16n8k16 MMA,
// cp.async double-buffered, channel-last-16 word layout.
// Tile: M=64 out-channels x N=384 pixels (4 rows). 8 warps = 2(M) x 4(rows).
// =====================================================================
#define SW_BYTES 18432   // 9*64*8w*4
#define SX_BYTES 18816   // 6*98*8w*4
#define CONV_SMEM (2*SW_BYTES + 2*SX_BYTES)   // 74496

__global__ __launch_bounds__(256, 2) void conv3x3_mma(
    const float* __restrict__ in,   // bf16 words, [B][CI/16][98][98][8w]
    const float* __restrict__ wt,   // repacked bf16 weights
    const float* __restrict__ bias, const float* __restrict__ gam,
    const float* __restrict__ bet,  const float* __restrict__ mu,
    const float* __restrict__ var,  float* __restrict__ out, // fp32 [B,CO,96,96]
    int CI, int CO)
{
    extern __shared__ uint8_t dynsm[];

    const int tid  = threadIdx.x;
    const int warp = tid >> 5;
    const int lane = tid & 31;
    const int g    = lane >> 2;
    const int tig  = lane & 3;
    const int wm   = warp >> 2;           // 0..1
    const int wn   = warp & 3;            // 0..3

    const int y0o = blockIdx.x * 4;
    const int co0 = blockIdx.y * 64;
    const int b   = blockIdx.z;
    const int nchunks = CI >> 4;

    const uint4* w4 = (const uint4*)wt;

    float acc[2][12][4];
#pragma unroll
    for (int mi = 0; mi < 2; mi++)
#pragma unroll
        for (int ni = 0; ni < 12; ni++)
#pragma unroll
            for (int q = 0; q < 4; q++) acc[mi][ni][q] = 0.f;

    auto load_chunk = [&](int chunk, int stg) {
        uint4* wdst = (uint4*)(dynsm + stg*SW_BYTES);
        const uint4* wsrc = w4 + ((size_t)chunk*9*CO + co0)*2;
        for (int l = tid; l < 1152; l += 256) {
            int rs = l >> 7, t = l & 127;
            cp16(wdst + l, wsrc + (size_t)rs*CO*2 + t);
        }
        uint4* xdst = (uint4*)(dynsm + 2*SW_BYTES + stg*SX_BYTES);
        const uint4* xsrc = (const uint4*)in +
            (((size_t)(b*nchunks + chunk))*PPIX + (size_t)y0o*98)*2;
        for (int l = tid; l < 1176; l += 256)
            cp16(xdst + l, xsrc + l);
    };

    load_chunk(0, 0);
    asm volatile("cp.async.commit_group;" ::: "memory");

    for (int chunk = 0; chunk < nchunks; chunk++) {
        const int st = chunk & 1;
        const bool more = (chunk + 1 < nchunks);
        if (more) {
            load_chunk(chunk + 1, st ^ 1);
            asm volatile("cp.async.commit_group;" ::: "memory");
            asm volatile("cp.async.wait_group 1;" ::: "memory");
        } else {
            asm volatile("cp.async.wait_group 0;" ::: "memory");
        }
        __syncthreads();

        const uint32_t (*W8)[64][8] = (const uint32_t (*)[64][8])(dynsm + st*SW_BYTES);
        const uint32_t (*X8)[98][8] = (const uint32_t (*)[98][8])(dynsm + 2*SW_BYTES + st*SX_BYTES);

#pragma unroll
        for (int r = 0; r < 3; r++) {
#pragma unroll
            for (int s = 0; s < 3; s++) {
                const int rs = r*3 + s;
                const int base0 = wm*32 + g;
                // tile mi rows: base0 + mi*16 (gives a0,a2), +8 (gives a1,a3)
                uint2 va00 = *(const uint2*)&W8[rs][base0     ][tig*2];
                uint2 va01 = *(const uint2*)&W8[rs][base0 +  8][tig*2];
                uint2 va10 = *(const uint2*)&W8[rs][base0 + 16][tig*2];
                uint2 va11 = *(const uint2*)&W8[rs][base0 + 24][tig*2];
                const int prow = wn + r;
#pragma unroll
                for (int ni = 0; ni < 12; ni++) {
                    uint2 vb = *(const uint2*)&X8[prow][ni*8 + g + s][tig*2];
                    mma_bf16(acc[0][ni], va00.x, va01.x, va00.y, va01.y, vb.x, vb.y);
                    mma_bf16(acc[1][ni], va10.x, va11.x, va10.y, va11.y, vb.x, vb.y);
                }
            }
        }
        __syncthreads();
    }

    // epilogue: BN + ReLU (fragment layout identical to tf32 path)
    const int orow = y0o + wn;
#pragma unroll
    for (int mi = 0; mi < 2; mi++) {
        int c_lo = co0 + wm*32 + mi*16 + g;
        int c_hi = c_lo + 8;
        float s_lo  = gam[c_lo] * rsqrtf(var[c_lo] + 1e-5f);
        float sh_lo = (bias[c_lo] - mu[c_lo]) * s_lo + bet[c_lo];
        float s_hi  = gam[c_hi] * rsqrtf(var[c_hi] + 1e-5f);
        float sh_hi = (bias[c_hi] - mu[c_hi]) * s_hi + bet[c_hi];
        float* plo = out + (size_t)(b*CO + c_lo)*NPIX + orow*96;
        float* phi = out + (size_t)(b*CO + c_hi)*NPIX + orow*96;
#pragma unroll
        for (int ni = 0; ni < 12; ni++) {
            int x = ni*8 + tig*2;
            *(float2*)(plo + x) = make_float2(fmaxf(acc[mi][ni][0]*s_lo + sh_lo, 0.f),
                                              fmaxf(acc[mi][ni][1]*s_lo + sh_lo, 0.f));
            *(float2*)(phi + x) = make_float2(fmaxf(acc[mi][ni][2]*s_hi + sh_hi, 0.f),
                                              fmaxf(acc[mi][ni][3]*s_hi + sh_hi, 0.f));
        }
    }
}

// =====================================================================
// Pad x -> g_xp [B][4][98][98][8w] bf16 words. grid = B4*4*7 row-bands.
// =====================================================================
__global__ __launch_bounds__(256) void pad_x_kernel(const float* __restrict__ x)
{
    const int z = blockIdx.x;
    const int band  = z % 7;
    const int chunk = (z / 7) & 3;
    const int b     = z / 28;
    uint32_t* dp = (uint32_t*)g_xp + ((size_t)(b*4 + chunk))*PPIX*8;
    const float* sp = x + ((size_t)b*C0IN + chunk*16)*NPIX;
    for (int i = threadIdx.x; i < 14*98*8; i += 256) {
        int j = i & 7;
        int p = i >> 3;
        int lrow = p / 98, col = p % 98;
        int row = band*14 + lrow;
        int pc = (j >> 1) + ((j & 1) << 2);
        int c_lo = pc*2;
        float vlo = 0.f, vhi = 0.f;
        if (row >= 1 && row <= 96 && col >= 1 && col <= 96) {
            vlo = sp[(size_t)(c_lo    )*NPIX + (row-1)*96 + (col-1)];
            vhi = sp[(size_t)(c_lo + 1)*NPIX + (row-1)*96 + (col-1)];
        }
        dp[((size_t)row*98 + col)*8 + j] = pack_bf16(vlo, vhi);
    }
}

// =====================================================================
// Branch construction into g_tp [B][12][98][98][8w] bf16 words.
// chunks 0-3: bilinear(maxpool2); 4-7: copy; 8-11: bilinear(avgpool2).
// One block per (b, chunk16, half8): grid B4*24, 1024 thr.
// half selects channels chunk*16 + half*8 .. +7 -> words j with (j&1)==half? no:
//   local pair pl (0..3) within half -> word j = pl*2 + half.
// =====================================================================
#define POOLPAD (HP*HP + 1)
#define BUILD_SMEM (8*POOLPAD*4)    // 73760 B

__global__ __launch_bounds__(1024) void build_t_kernel()
{
    extern __shared__ float pool[];   // [8 local ch][POOLPAD]
    const int z = blockIdx.x;         // 0..95
    const int half  = z & 1;
    const int chunk = (z >> 1) % 12;
    const int b     = z / 24;
    const int tid = threadIdx.x;
    uint32_t* dp = (uint32_t*)g_tp + ((size_t)(b*12 + chunk))*PPIX*8;
    const float* yb = g_y + ((size_t)b*192)*NPIX;
    const int c0 = chunk*16 + half*8;     // first of 8 channels this block owns

    if (chunk >= 4 && chunk < 8) {        // copy branch
        for (int i = tid; i < PPIX*4; i += 1024) {
            int pl = i & 3;
            int p  = i >> 2;
            int row = p / 98, col = p % 98;
            float vlo = 0.f, vhi = 0.f;
            if (row >= 1 && row <= 96 && col >= 1 && col <= 96) {
                const float* yp = yb + (size_t)(c0 + pl*2)*NPIX + (row-1)*96 + (col-1);
                vlo = yp[0];
                vhi = yp[NPIX];
            }
            dp[(size_t)p*8 + pl*2 + half] = pack_bf16(vlo, vhi);
        }
        return;
    }

    const bool is_max = (chunk < 4);
    for (int i = tid; i < 8*HP*HP; i += 1024) {
        int lc = i / (HP*HP);
        int idx = i % (HP*HP);
        int p = idx / HP, q = idx % HP;
        const float* yp = yb + (size_t)(c0 + lc)*NPIX;
        float a  = yp[(2*p)  *96 + 2*q    ];
        float bb = yp[(2*p)  *96 + 2*q + 1];
        float cc = yp[(2*p+1)*96 + 2*q    ];
        float dd = yp[(2*p+1)*96 + 2*q + 1];
        pool[lc*POOLPAD + idx] = is_max ? fmaxf(fmaxf(a,bb), fmaxf(cc,dd))
                                        : 0.25f*(a + bb + cc + dd);
    }
    __syncthreads();

    for (int i = tid; i < PPIX*4; i += 1024) {
        int pl = i & 3;
        int p  = i >> 2;
        int row = p / 98, col = p % 98;
        uint32_t word = 0;
        if (row >= 1 && row <= 96 && col >= 1 && col <= 96) {
            int h = row - 1, w = col - 1;
            float chf = fminf(fmaxf(0.5f*h - 0.25f, 0.f), 47.f);
            float cwf = fminf(fmaxf(0.5f*w - 0.25f, 0.f), 47.f);
            int hlo = (int)chf; int hhi = min(hlo + 1, 47); float hf = chf - hlo;
            int wlo = (int)cwf; int whi = min(wlo + 1, 47); float wf = cwf - wlo;
            const float* p0 = pool + (pl*2    )*POOLPAD;
            const float* p1 = pool + (pl*2 + 1)*POOLPAD;
            float t0 = p0[hlo*HP + wlo]*(1.f - wf) + p0[hlo*HP + whi]*wf;
            float b0 = p0[hhi*HP + wlo]*(1.f - wf) + p0[hhi*HP + whi]*wf;
            float t1 = p1[hlo*HP + wlo]*(1.f - wf) + p1[hlo*HP + whi]*wf;
            float b1 = p1[hhi*HP + wlo]*(1.f - wf) + p1[hhi*HP + whi]*wf;
            word = pack_bf16(t0*(1.f - hf) + b0*hf, t1*(1.f - hf) + b1*hf);
        }
        dp[(size_t)p*8 + pl*2 + half] = word;
    }
}

// =====================================================================
// Row L2-norm reciprocals for q and k.
// =====================================================================
__global__ __launch_bounds__(256) void rownorm_kernel()
{
    const int x = blockIdx.x;
    const bool isK = (x >= 768);
    const int r = x % 768;
    const int b = r / 192, c = r % 192;
    const float* p = g_t2 + (size_t)(b*C1OUT + (isK ? 192 : 0) + c) * NPIX;
    const int tid = threadIdx.x;
    float s = 0.f;
    for (int i = tid; i < NPIX/4; i += 256) {
        float4 v = ((const float4*)p)[i];
        s += v.x*v.x + v.y*v.y + v.z*v.z + v.w*v.w;
    }
    __shared__ float sm[256];
    sm[tid] = s; __syncthreads();
    for (int st = 128; st > 0; st >>= 1) {
        if (tid < st) sm[tid] += sm[tid + st];
        __syncthreads();
    }
    if (tid == 0) {
        float inv = 1.f / fmaxf(sqrtf(sm[0]), 1e-12f);
        if (isK) g_kn[r] = inv; else g_qn[r] = inv;
    }
}

// =====================================================================
// QK^T via tf32 MMA (split-k over 8 warps, smem reduce).
// =====================================================================
__global__ __launch_bounds__(256) void qk_mma_kernel(const float* __restrict__ temp)
{
    __shared__ __align__(16) uint8_t smraw[8*32*33*4];
    uint32_t (*Qs)[68] = (uint32_t(*)[68])smraw;
    uint32_t (*Ks)[68] = (uint32_t(*)[68])(smraw + 32*68*4);
    float (*sP)[32][33] = (float(*)[32][33])smraw;

    const int b = blockIdx.z;
    const int i0 = blockIdx.y * 32, j0 = blockIdx.x * 32;
    const int tid  = threadIdx.x;
    const int warp = tid >> 5;
    const int lane = tid & 31;
    const int g    = lane >> 2;
    const int tig  = lane & 3;

    const float* Q = g_t2 + (size_t)b * C1OUT * NPIX;
    const float* K = Q + (size_t)192 * NPIX;

    float acc[2][4][4];
#pragma unroll
    for (int mt = 0; mt < 2; mt++)
#pragma unroll
        for (int nt = 0; nt < 4; nt++)
#pragma unroll
            for (int q = 0; q < 4; q++) acc[mt][nt][q] = 0.f;

    const int kb = warp * 8;
    for (int kt = 0; kt < NPIX; kt += 64) {
        __syncthreads();
        for (int f = tid; f < 512; f += 256) {
            int row = f >> 4, kc = (f & 15) * 4;
            float4 q4 = *(const float4*)&Q[(size_t)(i0+row)*NPIX + kt + kc];
            float4 k4 = *(const float4*)&K[(size_t)(j0+row)*NPIX + kt + kc];
            *(uint4*)&Qs[row][kc] = make_uint4(f2tf(q4.x), f2tf(q4.y), f2tf(q4.z), f2tf(q4.w));
            *(uint4*)&Ks[row][kc] = make_uint4(f2tf(k4.x), f2tf(k4.y), f2tf(k4.z), f2tf(k4.w));
        }
        __syncthreads();

        uint32_t a[2][4];
#pragma unroll
        for (int mt = 0; mt < 2; mt++) {
            int r0 = mt*16 + g;
            a[mt][0] = Qs[r0    ][kb + tig];
            a[mt][1] = Qs[r0 + 8][kb + tig];
            a[mt][2] = Qs[r0    ][kb + tig + 4];
            a[mt][3] = Qs[r0 + 8][kb + tig + 4];
        }
#pragma unroll
        for (int nt = 0; nt < 4; nt++) {
            int jr = nt*8 + g;
            uint32_t b0 = Ks[jr][kb + tig];
            uint32_t b1 = Ks[jr][kb + tig + 4];
            mma_tf32(acc[0][nt], a[0][0], a[0][1], a[0][2], a[0][3], b0, b1);
            mma_tf32(acc[1][nt], a[1][0], a[1][1], a[1][2], a[1][3], b0, b1);
        }
    }

    __syncthreads();
#pragma unroll
    for (int mt = 0; mt < 2; mt++)
#pragma unroll
        for (int nt = 0; nt < 4; nt++) {
            int r = mt*16 + g, cix = nt*8 + tig*2;
            sP[warp][r    ][cix    ] = acc[mt][nt][0];
            sP[warp][r    ][cix + 1] = acc[mt][nt][1];
            sP[warp][r + 8][cix    ] = acc[mt][nt][2];
            sP[warp][r + 8][cix + 1] = acc[mt][nt][3];
        }
    __syncthreads();

    float tmp = temp[0];
    for (int o = tid; o < 1024; o += 256) {
        int row = o >> 5, col = o & 31;
        float s = 0.f;
#pragma unroll
        for (int w = 0; w < 8; w++) s += sP[w][row][col];
        g_att[(size_t)(b*192 + i0 + row)*192 + j0 + col] =
            s * g_qn[b*192 + i0 + row] * tmp * g_kn[b*192 + j0 + col];
    }
}

// =====================================================================
// Softmax over last dim (192).
// =====================================================================
__global__ __launch_bounds__(256) void softmax_kernel()
{
    const int row = blockIdx.x;          // 0..767
    float* p = g_att + (size_t)row * 192;
    const int t = threadIdx.x;
    __shared__ float sm[256];
    float v = (t < 192) ? p[t] : -3.0e38f;
    sm[t] = v; __syncthreads();
    for (int s = 128; s > 0; s >>= 1) {
        if (t < s) sm[t] = fmaxf(sm[t], sm[t+s]);
        __syncthreads();
    }
    float mx = sm[0]; __syncthreads();
    float e = (t < 192) ? expf(v - mx) : 0.f;
    sm[t] = e; __syncthreads();
    for (int s = 128; s > 0; s >>= 1) {
        if (t < s) sm[t] += sm[t+s];
        __syncthreads();
    }
    float inv = 1.f / sm[0];
    if (t < 192) p[t] = e * inv;
}

// =====================================================================
// O = A @ V via tf32 MMA. CTA tile 32(i) x 128(n); K=192 (j), chunk 32.
// =====================================================================
__global__ __launch_bounds__(256) void av_mma_kernel()
{
    __shared__ uint32_t As[32][196];
    __shared__ uint32_t Vs[128][36];

    const int b  = blockIdx.z;
    const int i0 = blockIdx.y * 32;
    const int n0 = blockIdx.x * 128;
    const int tid  = threadIdx.x;
    const int warp = tid >> 5;
    const int lane = tid & 31;
    const int g    = lane >> 2;
    const int tig  = lane & 3;

    const float* A = g_att + (size_t)b * 192 * 192;
    const float* V = g_t2 + ((size_t)b*C1OUT + 384) * NPIX;

#pragma unroll
    for (int j = 0; j < 24; j++) {
        int l = j*256 + tid;
        int r = l / 192, c = l % 192;
        As[r][c] = f2tf(A[(size_t)(i0 + r)*192 + c]);
    }

    float acc[2][2][4];
#pragma unroll
    for (int mt = 0; mt < 2; mt++)
#pragma unroll
        for (int nt = 0; nt < 2; nt++)
#pragma unroll
            for (int q = 0; q < 4; q++) acc[mt][nt][q] = 0.f;

    for (int kt = 0; kt < 192; kt += 32) {
        __syncthreads();
        for (int l = tid; l < 4096; l += 256) {
            int kk = l >> 7, nn = l & 127;
            Vs[nn][kk] = f2tf(V[(size_t)(kt + kk)*NPIX + n0 + nn]);
        }
        __syncthreads();

#pragma unroll
        for (int ks = 0; ks < 4; ks++) {
            const int ka = kt + ks*8;
            uint32_t a[2][4];
#pragma unroll
            for (int mt = 0; mt < 2; mt++) {
                int r0 = mt*16 + g;
                a[mt][0] = As[r0    ][ka + tig];
                a[mt][1] = As[r0 + 8][ka + tig];
                a[mt][2] = As[r0    ][ka + tig + 4];
                a[mt][3] = As[r0 + 8][ka + tig + 4];
            }
#pragma unroll
            for (int nt = 0; nt < 2; nt++) {
                int nr = warp*16 + nt*8 + g;
                uint32_t b0 = Vs[nr][ks*8 + tig];
                uint32_t b1 = Vs[nr][ks*8 + tig + 4];
                mma_tf32(acc[0][nt], a[0][0], a[0][1], a[0][2], a[0][3], b0, b1);
                mma_tf32(acc[1][nt], a[1][0], a[1][1], a[1][2], a[1][3], b0, b1);
            }
        }
    }

#pragma unroll
    for (int mt = 0; mt < 2; mt++) {
        int r = i0 + mt*16 + g;
#pragma unroll
        for (int nt = 0; nt < 2; nt++) {
            int nc = n0 + warp*16 + nt*8 + tig*2;
            *(float2*)&g_o[((size_t)(b*192) + r    )*NPIX + nc] =
                make_float2(acc[mt][nt][0], acc[mt][nt][1]);
            *(float2*)&g_o[((size_t)(b*192) + r + 8)*NPIX + nc] =
                make_float2(acc[mt][nt][2], acc[mt][nt][3]);
        }
    }
}

// =====================================================================
// Depthwise 3x3 conv (pad 1) + bias on g_o -> d_out.
// =====================================================================
__global__ __launch_bounds__(256) void dwconv_kernel(
    const float* __restrict__ w2, const float* __restrict__ b2,
    float* __restrict__ out)
{
    __shared__ float sIn[34][34];
    const int tx = threadIdx.x, ty = threadIdx.y;
    const int tid = ty*16 + tx;
    const int z = blockIdx.z;            // 0..767
    const int b = z / 192, c = z % 192;
    const int y0 = blockIdx.y*32, x0 = blockIdx.x*32;
    const float* ip = g_o + (size_t)(b*192 + c) * NPIX;

    for (int l = tid; l < 34*34; l += 256) {
        int i = l / 34, j = l % 34;
        int gy = y0 - 1 + i, gx = x0 - 1 + j;
        float v = 0.f;
        if ((unsigned)gy < 96u && (unsigned)gx < 96u) v = ip[gy*96 + gx];
        ((float*)sIn)[l] = v;
    }
    __syncthreads();

    float wv[9];
#pragma unroll
    for (int k = 0; k < 9; k++) wv[k] = w2[c*9 + k];
    float bb = b2[c];

    float iv[4][4];
#pragma unroll
    for (int r = 0; r < 4; r++)
#pragma unroll
        for (int cc = 0; cc < 4; cc++) iv[r][cc] = sIn[2*ty + r][2*tx + cc];

    float a00 = bb, a01 = bb, a10 = bb, a11 = bb;
#pragma unroll
    for (int ky = 0; ky < 3; ky++)
#pragma unroll
        for (int kx = 0; kx < 3; kx++) {
            float wk = wv[ky*3 + kx];
            a00 += iv[ky  ][kx  ]*wk;
            a01 += iv[ky  ][kx+1]*wk;
            a10 += iv[ky+1][kx  ]*wk;
            a11 += iv[ky+1][kx+1]*wk;
        }
    const int oy = y0 + 2*ty, ox = x0 + 2*tx;
    float* op = out + (size_t)(b*192 + c)*NPIX + oy*96 + ox;
    op[0] = a00; op[1] = a01; op[96] = a10; op[97] = a11;
}

// =====================================================================
// Launcher
// =====================================================================
extern "C" void kernel_launch(void* const* d_in, const int* in_sizes, int n_in,
                              void* d_out, int out_size)
{
    const float* x    = (const float*)d_in[0];
    const float* w0   = (const float*)d_in[1];
    const float* b0   = (const float*)d_in[2];
    const float* g0   = (const float*)d_in[3];
    const float* be0  = (const float*)d_in[4];
    const float* m0   = (const float*)d_in[5];
    const float* v0   = (const float*)d_in[6];
    const float* w1   = (const float*)d_in[7];
    const float* b1   = (const float*)d_in[8];
    const float* g1   = (const float*)d_in[9];
    const float* be1  = (const float*)d_in[10];
    const float* m1   = (const float*)d_in[11];
    const float* v1   = (const float*)d_in[12];
    const float* temp = (const float*)d_in[13];
    const float* w2   = (const float*)d_in[14];
    const float* b2   = (const float*)d_in[15];
    float* out = (float*)d_out;

    float *pxp, *py, *ptp, *pt2, *pw0t, *pw1t;
    cudaGetSymbolAddress((void**)&pxp,  g_xp);
    cudaGetSymbolAddress((void**)&py,   g_y);
    cudaGetSymbolAddress((void**)&ptp,  g_tp);
    cudaGetSymbolAddress((void**)&pt2,  g_t2);
    cudaGetSymbolAddress((void**)&pw0t, g_w0t);
    cudaGetSymbolAddress((void**)&pw1t, g_w1t);

    cudaFuncSetAttribute(conv3x3_mma,
        cudaFuncAttributeMaxDynamicSharedMemorySize, CONV_SMEM);
    cudaFuncSetAttribute(build_t_kernel,
        cudaFuncAttributeMaxDynamicSharedMemorySize, BUILD_SMEM);

    // weight repacks (bf16 words)
    repack_w_kernel<<<216, 256>>>(w0, pw0t, C0IN, C0OUT);
    repack_w_kernel<<<1024, 256>>>(w1, pw1t, C0OUT, C1OUT);

    // pad x -> g_xp (bf16 words, channel-last-16)
    pad_x_kernel<<<B4*4*7, 256>>>(x);

    // conv0 + bn + relu : g_xp -> g_y
    conv3x3_mma<<<dim3(24, C0OUT/64, B4), 256, CONV_SMEM>>>(
        pxp, pw0t, b0, g0, be0, m0, v0, py, C0IN, C0OUT);

    // branches -> g_tp (bf16 words)
    build_t_kernel<<<B4*24, 1024, BUILD_SMEM>>>();

    // conv1 + bn + relu : g_tp -> g_t2
    conv3x3_mma<<<dim3(24, C1OUT/64, B4), 256, CONV_SMEM>>>(
        ptp, pw1t, b1, g1, be1, m1, v1, pt2, C0OUT, C1OUT);

    // q/k row norms
    rownorm_kernel<<<2*B4*192, 256>>>();

    // attention logits (tensor cores, tf32)
    qk_mma_kernel<<<dim3(6, 6, B4), 256>>>(temp);

    // softmax
    softmax_kernel<<<B4*192, 256>>>();

    // attn @ v (tensor cores, tf32)
    av_mma_kernel<<<dim3(72, 6, B4), 256>>>();

    // depthwise conv + bias -> output
    dwconv_kernel<<<dim3(3, 3, B4*192), dim3(16,16)>>>(w2, b2, out);
}